// round 11
// baseline (speedup 1.0000x reference)
#include <cuda_runtime.h>
#include <cuda_bf16.h>
#include <cstdint>

#define CIN 128
#define KNN 16
#define NMAX 8192
#define EPS 1e-5f
#define SLOPE 0.01f
#define GRID 8
#define NCELL (GRID * GRID * GRID)
#define CELLH (1.0f / GRID)
#define PADK 72   // bf16 stride (qkv kernel)
#define PADB 80   // byte stride for int8 tiles (16B-aligned rows, conflict-free)

// ---------------- scratch (static device memory; no allocations) ----------------
__device__ int   g_idx[NMAX * KNN];
__device__ int   g_cid[NMAX];
__device__ int   g_cellstart[NCELL + 1];
__device__ __align__(16) float4 g_cellpts[NMAX];
__device__ __align__(16) float g_Q[NMAX * CIN];
__device__ __align__(16) float g_K[NMAX * CIN];
__device__ __align__(16) float g_V[NMAX * CIN];
__device__ __align__(16) float g_w2[(size_t)NMAX * KNN * CIN];
__device__ float g_stat[4 * CIN];   // [0:128)=sum1 [128:256)=sq1 [256:384)=sum2 [384:512)=sq2
__device__ __align__(16) __nv_bfloat16 g_Wbh[4 * CIN * CIN];  // Wq,Wk,Wv bf16-hi
__device__ __align__(16) __nv_bfloat16 g_Wbl[4 * CIN * CIN];  // Wq,Wk,Wv bf16-lo
__device__ __align__(16) char g_Wl1[CIN * CIN];               // Wl int8 hi digit
__device__ __align__(16) char g_Wl0[CIN * CIN];               // Wl int8 lo digit
__device__ float g_scales[2];                                  // [0]=t1 (B step), [1]=s1 (A step)

__device__ __forceinline__ int cell1(float x) {
    int c = (int)(x * (float)GRID);
    return c < 0 ? 0 : (c > GRID - 1 ? GRID - 1 : c);
}

__device__ __forceinline__ uint32_t smem_u32(const void* p) {
    uint32_t a;
    asm("{ .reg .u64 t; cvta.to.shared.u64 t, %1; cvt.u32.u64 %0, t; }" : "=r"(a) : "l"(p));
    return a;
}
__device__ __forceinline__ void cp16(uint32_t dst, const void* src) {
    asm volatile("cp.async.cg.shared.global [%0], [%1], 16;" :: "r"(dst), "l"(src));
}
#define CP_COMMIT() asm volatile("cp.async.commit_group;")
#define CP_WAIT0()  asm volatile("cp.async.wait_group 0;" ::: "memory")

__device__ __forceinline__ void ldsm4(uint32_t* r, uint32_t addr) {
    asm volatile("ldmatrix.sync.aligned.m8n8.x4.shared.b16 {%0,%1,%2,%3}, [%4];"
        : "=r"(r[0]), "=r"(r[1]), "=r"(r[2]), "=r"(r[3]) : "r"(addr));
}

__device__ __forceinline__ void split_pair(float x0, float x1, uint32_t& hp, uint32_t& lp) {
    __nv_bfloat16 h0 = __float2bfloat16(x0);
    __nv_bfloat16 h1 = __float2bfloat16(x1);
    __nv_bfloat16 l0 = __float2bfloat16(x0 - __bfloat162float(h0));
    __nv_bfloat16 l1 = __float2bfloat16(x1 - __bfloat162float(h1));
    hp = ((uint32_t)__bfloat16_as_ushort(h1) << 16) | __bfloat16_as_ushort(h0);
    lp = ((uint32_t)__bfloat16_as_ushort(l1) << 16) | __bfloat16_as_ushort(l0);
}

__device__ __forceinline__ void mma16816(float* d, const uint32_t* a, const uint32_t* b) {
    asm volatile(
        "mma.sync.aligned.m16n8k16.row.col.f32.bf16.bf16.f32 "
        "{%0,%1,%2,%3}, {%4,%5,%6,%7}, {%8,%9}, {%0,%1,%2,%3};"
        : "+f"(d[0]), "+f"(d[1]), "+f"(d[2]), "+f"(d[3])
        : "r"(a[0]), "r"(a[1]), "r"(a[2]), "r"(a[3]), "r"(b[0]), "r"(b[1]));
}

__device__ __forceinline__ void imma16832(int* d, const uint32_t* a, const uint32_t* b) {
    asm volatile(
        "mma.sync.aligned.m16n8k32.row.col.s32.s8.s8.s32 "
        "{%0,%1,%2,%3}, {%4,%5,%6,%7}, {%8,%9}, {%0,%1,%2,%3};"
        : "+r"(d[0]), "+r"(d[1]), "+r"(d[2]), "+r"(d[3])
        : "r"(a[0]), "r"(a[1]), "r"(a[2]), "r"(a[3]), "r"(b[0]), "r"(b[1]));
}

__device__ __forceinline__ int clamp127(int v) {
    return v < -127 ? -127 : (v > 127 ? 127 : v);
}

// ---------------- k_build ----------------
// b0: grid build + stat zero; b1..b6: bf16 presplit Wq/Wk/Wv; b7: Wl int8 + scales
__global__ void __launch_bounds__(1024) k_build(
    const float* __restrict__ xyz_i,
    const float* __restrict__ Wq, const float* __restrict__ Wk,
    const float* __restrict__ Wv, const float* __restrict__ Wl,
    const float* __restrict__ g1, const float* __restrict__ b1, int N)
{
    int t = threadIdx.x;
    int b = blockIdx.x;

    if (b >= 1 && b <= 6) {
        uint32_t* oh = (uint32_t*)g_Wbh;
        uint32_t* ol = (uint32_t*)g_Wbl;
        int e0 = (b - 1) * 4096;
#pragma unroll
        for (int v = 0; v < 4; v++) {
            int e = e0 + v * 1024 + t;     // e < 24576 (3 matrices of 8192 pairs)
            int m = e >> 13;
            int off = (e & 8191) * 2;
            const float* W = (m == 0) ? Wq : (m == 1 ? Wk : Wv);
            float2 x = *(const float2*)(W + off);
            uint32_t hp, lp;
            split_pair(x.x, x.y, hp, lp);
            oh[e] = hp;
            ol[e] = lp;
        }
        return;
    }

    if (b == 7) {  // int8 presplit of Wl + global scales
        __shared__ float red[1024];
        float mx = 0.f;
        for (int i = t; i < CIN * CIN; i += 1024) mx = fmaxf(mx, fabsf(Wl[i]));
        red[t] = mx; __syncthreads();
        for (int o = 512; o; o >>= 1) {
            if (t < o) red[t] = fmaxf(red[t], red[t + o]);
            __syncthreads();
        }
        float t1 = red[0] / 127.f;
        if (t1 <= 0.f) t1 = 1.f;
        __syncthreads();
        float gb = (t < 128) ? 8.f * fabsf(g1[t]) + fabsf(b1[t]) : 0.f;
        red[t] = gb; __syncthreads();
        for (int o = 512; o; o >>= 1) {
            if (t < o) red[t] = fmaxf(red[t], red[t + o]);
            __syncthreads();
        }
        float s1 = red[0] / 127.f;
        if (s1 <= 0.f) s1 = 1.f;
        if (t == 0) { g_scales[0] = t1; g_scales[1] = s1; }
        float it1 = 1.f / t1, it0 = 128.f / t1;
        for (int i = t; i < CIN * CIN; i += 1024) {
            float w = Wl[i];
            int q1 = clamp127(__float2int_rn(w * it1));
            float r = fmaf(-t1, (float)q1, w);
            int q0 = clamp127(__float2int_rn(r * it0));
            g_Wl1[i] = (char)q1;
            g_Wl0[i] = (char)q0;
        }
        return;
    }

    // b == 0: grid build
    __shared__ int scnt[NCELL];
    __shared__ int spre[NCELL];
    __shared__ int scur[NCELL];

    if (t < NCELL) scnt[t] = 0;
    if (t < 4 * CIN) g_stat[t] = 0.f;
    __syncthreads();

    for (int i = t; i < N; i += 1024) {
        float x = xyz_i[i * 3 + 0], y = xyz_i[i * 3 + 1], z = xyz_i[i * 3 + 2];
        int cid = (cell1(z) * GRID + cell1(y)) * GRID + cell1(x);
        g_cid[i] = cid;
        atomicAdd(&scnt[cid], 1);
    }
    __syncthreads();

    if (t < NCELL) spre[t] = scnt[t];
    __syncthreads();
    for (int o = 1; o < NCELL; o <<= 1) {
        int v = (t >= o && t < NCELL) ? spre[t - o] : 0;
        __syncthreads();
        if (t < NCELL) spre[t] += v;
        __syncthreads();
    }
    if (t < NCELL) {
        int excl = spre[t] - scnt[t];
        g_cellstart[t] = excl;
        scur[t] = excl;
    }
    if (t == NCELL - 1) g_cellstart[NCELL] = spre[NCELL - 1];
    __syncthreads();

    for (int i = t; i < N; i += 1024) {
        float x = xyz_i[i * 3 + 0], y = xyz_i[i * 3 + 1], z = xyz_i[i * 3 + 2];
        int slot = atomicAdd(&scur[g_cid[i]], 1);
        g_cellpts[slot] = make_float4(x, y, z, __int_as_float(i));
    }
}

// ---------------- serial fallback knn (exact, shell expansion) ----------------
__device__ void knn_serial(int q, float qx, float qy, float qz, int cx, int cy, int cz) {
    float bd[KNN];
    int   bi[KNN];
#pragma unroll
    for (int s = 0; s < KNN; s++) { bd[s] = 1e30f; bi[s] = -1; }
    float curmax = 1e30f;
    int maxslot = 0;
    for (int R = 0; R < GRID; R++) {
        int zlo = cz - R < 0 ? 0 : cz - R, zhi = cz + R > GRID - 1 ? GRID - 1 : cz + R;
        int ylo = cy - R < 0 ? 0 : cy - R, yhi = cy + R > GRID - 1 ? GRID - 1 : cy + R;
        int xlo = cx - R < 0 ? 0 : cx - R, xhi = cx + R > GRID - 1 ? GRID - 1 : cx + R;
        for (int zz = zlo; zz <= zhi; zz++) {
            int adz = zz - cz; adz = adz < 0 ? -adz : adz;
            for (int yy = ylo; yy <= yhi; yy++) {
                int ady = yy - cy; ady = ady < 0 ? -ady : ady;
                int rowmax = adz > ady ? adz : ady;
                for (int xx = xlo; xx <= xhi; xx++) {
                    int adx = xx - cx; adx = adx < 0 ? -adx : adx;
                    int cheb = rowmax > adx ? rowmax : adx;
                    if (cheb != R) continue;
                    int cellid = (zz * GRID + yy) * GRID + xx;
                    int s0 = g_cellstart[cellid];
                    int s1 = g_cellstart[cellid + 1];
                    for (int s = s0; s < s1; s++) {
                        float4 p = g_cellpts[s];
                        float dx = qx - p.x, dy = qy - p.y, dz = qz - p.z;
                        float d2 = fmaf(dx, dx, fmaf(dy, dy, dz * dz));
                        if (d2 < curmax) {
                            int j = __float_as_int(p.w);
#pragma unroll
                            for (int u = 0; u < KNN; u++)
                                if (u == maxslot) { bd[u] = d2; bi[u] = j; }
                            curmax = -1.f;
#pragma unroll
                            for (int u = 0; u < KNN; u++)
                                if (bd[u] > curmax) { curmax = bd[u]; maxslot = u; }
                        }
                    }
                }
            }
        }
        float reach = (float)R * CELLH;
        if (curmax <= reach * reach) break;
    }
#pragma unroll
    for (int s = 0; s < KNN; s++) g_idx[q * KNN + s] = bi[s];
}

// ---------------- warp-per-query knn + fused BN1 stats ----------------
__global__ void __launch_bounds__(256) k_knn_warp(const float* __restrict__ xyz_last, int N) {
    __shared__ int s_pre[8][12];
    __shared__ int s_s0[8][12];
    __shared__ float s_sum[128], s_sq[128];
    int w = threadIdx.x >> 5;
    int lid = threadIdx.x & 31;
    int q = (blockIdx.x * 256 + threadIdx.x) >> 5;

    if (threadIdx.x < 128) { s_sum[threadIdx.x] = 0.f; s_sq[threadIdx.x] = 0.f; }
    __syncthreads();

    bool valid = (q < N);
    if (valid) {
        float qx = xyz_last[q * 3 + 0];
        float qy = xyz_last[q * 3 + 1];
        float qz = xyz_last[q * 3 + 2];
        int cx = cell1(qx), cy = cell1(qy), cz = cell1(qz);

        int zlo = cz - 1 < 0 ? 0 : cz - 1, zhi = cz + 1 > GRID - 1 ? GRID - 1 : cz + 1;
        int ylo = cy - 1 < 0 ? 0 : cy - 1, yhi = cy + 1 > GRID - 1 ? GRID - 1 : cy + 1;
        int xlo = cx - 1 < 0 ? 0 : cx - 1, xhi = cx + 1 > GRID - 1 ? GRID - 1 : cx + 1;
        int ny = yhi - ylo + 1;
        int nrows = (zhi - zlo + 1) * ny;

        int s0 = 0, len = 0;
        if (lid < nrows) {
            int zz = zlo + lid / ny;
            int yy = ylo + lid % ny;
            int cbase = (zz * GRID + yy) * GRID;
            s0 = g_cellstart[cbase + xlo];
            len = g_cellstart[cbase + xhi + 1] - s0;
        }
        int pre = len;
#pragma unroll
        for (int o = 1; o < 32; o <<= 1) {
            int v = __shfl_up_sync(0xFFFFFFFFu, pre, o);
            if (lid >= o) pre += v;
        }
        int T = __shfl_sync(0xFFFFFFFFu, pre, 31);
        int myStart = pre - len;

        if (lid < 12) { s_pre[w][lid] = 0x7FFFFFFF; s_s0[w][lid] = 0; }
        __syncwarp();
        if (lid <= nrows && lid < 10) s_pre[w][lid] = myStart;
        if (lid < nrows) s_s0[w][lid] = s0;
        __syncwarp();

        float bd[KNN];
        int   bi[KNN];
#pragma unroll
        for (int s = 0; s < KNN; s++) { bd[s] = 1e30f; bi[s] = -1; }
        float curmax = 1e30f;
        int maxslot = 0;

        int niter = (T + 31) >> 5;
        for (int it = 0; it < niter; it++) {
            int c = it * 32 + lid;
            if (c < T) {
                int j = 0;
#pragma unroll
                for (int i = 1; i <= 9; i++) j += (c >= s_pre[w][i]) ? 1 : 0;
                int slot = s_s0[w][j] + (c - s_pre[w][j]);
                float4 p = g_cellpts[slot];
                float dx = qx - p.x, dy = qy - p.y, dz = qz - p.z;
                float d2 = fmaf(dx, dx, fmaf(dy, dy, dz * dz));
                if (d2 < curmax) {
                    int ji = __float_as_int(p.w);
#pragma unroll
                    for (int u = 0; u < KNN; u++)
                        if (u == maxslot) { bd[u] = d2; bi[u] = ji; }
                    curmax = -1.f;
#pragma unroll
                    for (int u = 0; u < KNN; u++)
                        if (bd[u] > curmax) { curmax = bd[u]; maxslot = u; }
                }
            }
        }

        float lmin = 1e30f;
        int lslot = 0;
#pragma unroll
        for (int s = 0; s < KNN; s++)
            if (bd[s] < lmin) { lmin = bd[s]; lslot = s; }

        float d16 = 0.f;
        int myres = -1;
        for (int r = 0; r < KNN; r++) {
            float v = lmin;
            int wl = lid;
#pragma unroll
            for (int o = 16; o; o >>= 1) {
                float ov = __shfl_xor_sync(0xFFFFFFFFu, v, o);
                int owl = __shfl_xor_sync(0xFFFFFFFFu, wl, o);
                if (ov < v || (ov == v && owl < wl)) { v = ov; wl = owl; }
            }
            int myidx = -1;
#pragma unroll
            for (int s = 0; s < KNN; s++)
                if (s == lslot) myidx = bi[s];
            int wi = __shfl_sync(0xFFFFFFFFu, myidx, wl);
            d16 = v;
            if (lid == r) myres = wi;
            if (lid == wl) {
#pragma unroll
                for (int s = 0; s < KNN; s++)
                    if (s == lslot) bd[s] = 1e30f;
                lmin = 1e30f; lslot = 0;
#pragma unroll
                for (int s = 0; s < KNN; s++)
                    if (bd[s] < lmin) { lmin = bd[s]; lslot = s; }
            }
        }

        if (d16 <= CELLH * CELLH) {
            if (lid < KNN) g_idx[q * KNN + lid] = myres;
        } else {
            if (lid == 0) knn_serial(q, qx, qy, qz, cx, cy, cz);
        }
        __syncwarp();

        {
            int cb = lid * 4;
            float4 Qv = *(const float4*)(g_Q + (size_t)q * 128 + cb);
            float S0 = 0.f, S1 = 0.f, S2 = 0.f, S3 = 0.f;
            float T0 = 0.f, T1 = 0.f, T2 = 0.f, T3 = 0.f;
#pragma unroll
            for (int k = 0; k < KNN; k++) {
                int j = g_idx[q * KNN + k];
                float4 kv = *(const float4*)(g_K + (size_t)j * 128 + cb);
                S0 += kv.x; T0 = fmaf(kv.x, kv.x, T0);
                S1 += kv.y; T1 = fmaf(kv.y, kv.y, T1);
                S2 += kv.z; T2 = fmaf(kv.z, kv.z, T2);
                S3 += kv.w; T3 = fmaf(kv.w, kv.w, T3);
            }
            atomicAdd(&s_sum[cb + 0], 16.f * Qv.x - S0);
            atomicAdd(&s_sum[cb + 1], 16.f * Qv.y - S1);
            atomicAdd(&s_sum[cb + 2], 16.f * Qv.z - S2);
            atomicAdd(&s_sum[cb + 3], 16.f * Qv.w - S3);
            atomicAdd(&s_sq[cb + 0], fmaf(16.f * Qv.x, Qv.x, fmaf(-2.f * Qv.x, S0, T0)));
            atomicAdd(&s_sq[cb + 1], fmaf(16.f * Qv.y, Qv.y, fmaf(-2.f * Qv.y, S1, T1)));
            atomicAdd(&s_sq[cb + 2], fmaf(16.f * Qv.z, Qv.z, fmaf(-2.f * Qv.z, S2, T2)));
            atomicAdd(&s_sq[cb + 3], fmaf(16.f * Qv.w, Qv.w, fmaf(-2.f * Qv.w, S3, T3)));
        }
    }
    __syncthreads();
    if (threadIdx.x < 128) {
        atomicAdd(&g_stat[threadIdx.x], s_sum[threadIdx.x]);
        atomicAdd(&g_stat[128 + threadIdx.x], s_sq[threadIdx.x]);
    }
}

// ---------------- QKV GEMM (bf16 3-term, unchanged structure, mode-0 only) ------
#define TILEB (128 * PADK * 2)
#define SM_AHI 0
#define SM_ALO TILEB
#define SM_BHI (2 * TILEB)
#define SM_BLO (3 * TILEB)
#define QKV_SMEM (4 * TILEB + 256)

__global__ void __launch_bounds__(256, 2) k_qkv_gemm(
    const float* __restrict__ fea_i, const float* __restrict__ fea_last)
{
    extern __shared__ char smem[];
    int t = threadIdx.x;
    int lane = t & 31, wid = t >> 5;
    int g = lane >> 2, c4 = lane & 3;
    int wm = wid & 3, wn = wid >> 2;
    int row0 = blockIdx.x * 128;

    char* Ah = smem + SM_AHI;
    char* Al = smem + SM_ALO;
    char* Bh = smem + SM_BHI;
    char* Bl = smem + SM_BLO;

    int wsel = blockIdx.y;
    const float* Asrc = (wsel == 0) ? fea_last : fea_i;
    float* C = (wsel == 0) ? g_Q : (wsel == 1 ? g_K : g_V);

    float acc[2][8][4];
#pragma unroll
    for (int mf = 0; mf < 2; mf++)
#pragma unroll
        for (int nf = 0; nf < 8; nf++)
#pragma unroll
            for (int e = 0; e < 4; e++) acc[mf][nf][e] = 0.f;

    int pr = t >> 1;
    int pch = (t & 1) * 32;

    const __nv_bfloat16* Wsh = g_Wbh + wsel * CIN * CIN;
    const __nv_bfloat16* Wsl = g_Wbl + wsel * CIN * CIN;

    int quad = lane >> 3, lr = lane & 7;
    int aoffe = (wm * 32 + (quad & 1) * 8 + lr) * PADK + (quad >> 1) * 8;
    int boffe = (wn * 64 + (quad >> 1) * 8 + lr) * PADK + (quad & 1) * 8;
    uint32_t uAh = smem_u32(Ah), uAl = smem_u32(Al);
    uint32_t uBh = smem_u32(Bh), uBl = smem_u32(Bl);

#pragma unroll 1
    for (int pass = 0; pass < 2; pass++) {
        int kk0 = pass * 64;
        {
            const __nv_bfloat16* sh = Wsh + pr * 128 + kk0 + pch;
            const __nv_bfloat16* sl = Wsl + pr * 128 + kk0 + pch;
            uint32_t dh = smem_u32(Bh + (pr * PADK + pch) * 2);
            uint32_t dl = smem_u32(Bl + (pr * PADK + pch) * 2);
#pragma unroll
            for (int c = 0; c < 4; c++) {
                cp16(dh + c * 16, sh + c * 8);
                cp16(dl + c * 16, sl + c * 8);
            }
            CP_COMMIT();
        }
        {
            int cg = kk0 + 2 * lane;
#pragma unroll
            for (int r = 0; r < 16; r++) {
                int row = wid * 16 + r;
                float2 av = *(const float2*)(Asrc + (size_t)(row0 + row) * 128 + cg);
                uint32_t hp, lp;
                split_pair(av.x, av.y, hp, lp);
                int off = (row * PADK + 2 * lane) * 2;
                *(uint32_t*)(Ah + off) = hp;
                *(uint32_t*)(Al + off) = lp;
            }
        }
        CP_WAIT0();
        __syncthreads();

#pragma unroll
        for (int s = 0; s < 4; s++) {
            int ke = s * 16;
            uint32_t ah[8], al[8], bh[16], bl[16];
            ldsm4(&ah[0], uAh + (aoffe + ke) * 2);
            ldsm4(&ah[4], uAh + (aoffe + 16 * PADK + ke) * 2);
            ldsm4(&al[0], uAl + (aoffe + ke) * 2);
            ldsm4(&al[4], uAl + (aoffe + 16 * PADK + ke) * 2);
#pragma unroll
            for (int j = 0; j < 4; j++) {
                ldsm4(&bh[4 * j], uBh + (boffe + j * 16 * PADK + ke) * 2);
                ldsm4(&bl[4 * j], uBl + (boffe + j * 16 * PADK + ke) * 2);
            }
#pragma unroll
            for (int mf = 0; mf < 2; mf++)
#pragma unroll
                for (int nf = 0; nf < 8; nf++) {
                    mma16816(acc[mf][nf], &ah[4 * mf], &bh[2 * nf]);
                    mma16816(acc[mf][nf], &al[4 * mf], &bh[2 * nf]);
                    mma16816(acc[mf][nf], &ah[4 * mf], &bl[2 * nf]);
                }
        }
        __syncthreads();
    }

#pragma unroll
    for (int mf = 0; mf < 2; mf++)
#pragma unroll
        for (int nf = 0; nf < 8; nf++) {
            int row = row0 + wm * 32 + mf * 16 + g;
            int col = wn * 64 + nf * 8 + 2 * c4;
            *(float2*)(C + (size_t)row * 128 + col) =
                make_float2(acc[mf][nf][0], acc[mf][nf][1]);
            *(float2*)(C + (size_t)(row + 8) * 128 + col) =
                make_float2(acc[mf][nf][2], acc[mf][nf][3]);
        }
}

// ---------------- W GEMM: int8 two-digit split, m16n8k32 -------------------------
// block tile 64(M) x 128(N), grid NK/64, 256 threads (8 warps, warp-tile 16x64)
#define W_A1 0
#define W_A0 (64 * PADB)                  // 5120
#define W_B1 (2 * 64 * PADB)              // 10240
#define W_B0 (W_B1 + 128 * PADB)          // 20480
#define W_AFF (W_B0 + 128 * PADB)         // 30720 (256 floats)
#define W_SUM (W_AFF + 1024)
#define W_SQ  (W_SUM + 512)
#define W_SMEM (W_SQ + 512)               // 32768

__global__ void __launch_bounds__(256, 2) k_w_gemm(
    const float* __restrict__ g1, const float* __restrict__ b1, float invc)
{
    extern __shared__ char smem[];
    int t = threadIdx.x;
    int lane = t & 31, wid = t >> 5;
    int g = lane >> 2, c4 = lane & 3;
    int wm = wid & 3, wn = wid >> 2;
    int row0 = blockIdx.x * 64;

    char* A1c = smem + W_A1;
    char* A0c = smem + W_A0;
    char* B1c = smem + W_B1;
    char* B0c = smem + W_B0;
    float* s_aff = (float*)(smem + W_AFF);
    float* s_sum = (float*)(smem + W_SUM);
    float* s_sq  = (float*)(smem + W_SQ);

    if (t < 128) {
        float mean = g_stat[t] * invc;
        float var  = g_stat[128 + t] * invc - mean * mean;
        float sc = g1[t] * rsqrtf(var + EPS);
        s_aff[t] = sc;
        s_aff[128 + t] = b1[t] - mean * sc;
        s_sum[t] = 0.f;
        s_sq[t]  = 0.f;
    }
    __syncthreads();

    float s1v = g_scales[1];
    float is1 = 1.f / s1v;
    float is0 = 128.f / s1v;

    float facc[8][4];
#pragma unroll
    for (int nf = 0; nf < 8; nf++)
#pragma unroll
        for (int e = 0; e < 4; e++) facc[nf][e] = 0.f;

    int quad = lane >> 3, lr = lane & 7;
    int aoffr = (wm * 16 + (quad & 1) * 8 + lr) * PADB + (quad >> 1) * 16;
    int boffr = (wn * 64 + (quad >> 1) * 8 + lr) * PADB + (quad & 1) * 16;
    uint32_t uA1 = smem_u32(A1c), uA0 = smem_u32(A0c);
    uint32_t uB1 = smem_u32(B1c), uB0 = smem_u32(B0c);

    int pr = t >> 1, half = t & 1;

#pragma unroll 1
    for (int pass = 0; pass < 2; pass++) {
        int kk0 = pass * 64;
        // ---- B slices via cp.async (int8 presplit in gmem)
        {
            const char* s1p = g_Wl1 + pr * 128 + kk0 + half * 32;
            const char* s0p = g_Wl0 + pr * 128 + kk0 + half * 32;
            uint32_t d1 = uB1 + pr * PADB + half * 32;
            uint32_t d0 = uB0 + pr * PADB + half * 32;
            cp16(d1, s1p); cp16(d1 + 16, s1p + 16);
            cp16(d0, s0p); cp16(d0 + 16, s0p + 16);
            CP_COMMIT();
        }
        // ---- A gather + affine + leaky + int8 two-digit quant (warp-per-row)
        {
            int cg = kk0 + 2 * lane;
            float sca = s_aff[cg], scb = s_aff[cg + 1];
            float sha = s_aff[128 + cg], shb = s_aff[128 + cg + 1];
#pragma unroll
            for (int r = 0; r < 8; r++) {
                int row = wid * 8 + r;
                int nk = row0 + row;
                int n = nk >> 4;
                int j = g_idx[nk];
                float2 qv = *(const float2*)(g_Q + (size_t)n * 128 + cg);
                float2 kv = *(const float2*)(g_K + (size_t)j * 128 + cg);
                float w0 = fmaf(qv.x - kv.x, sca, sha);
                float w1 = fmaf(qv.y - kv.y, scb, shb);
                w0 = w0 >= 0.f ? w0 : SLOPE * w0;
                w1 = w1 >= 0.f ? w1 : SLOPE * w1;
                int q1a = clamp127(__float2int_rn(w0 * is1));
                int q1b = clamp127(__float2int_rn(w1 * is1));
                float r0 = fmaf(-s1v, (float)q1a, w0);
                float r1 = fmaf(-s1v, (float)q1b, w1);
                int q0a = clamp127(__float2int_rn(r0 * is0));
                int q0b = clamp127(__float2int_rn(r1 * is0));
                int off = row * PADB + 2 * lane;
                *(unsigned short*)(A1c + off) =
                    (unsigned short)((q1a & 0xFF) | ((q1b & 0xFF) << 8));
                *(unsigned short*)(A0c + off) =
                    (unsigned short)((q0a & 0xFF) | ((q0b & 0xFF) << 8));
            }
        }
        CP_WAIT0();
        __syncthreads();

        // ---- mainloop: 2 k32-steps; terms q1B1 (hi), q0B1 + q1B0 (cross)
        int iH[8][4], iX[8][4];
#pragma unroll
        for (int nf = 0; nf < 8; nf++)
#pragma unroll
            for (int e = 0; e < 4; e++) { iH[nf][e] = 0; iX[nf][e] = 0; }

#pragma unroll
        for (int s = 0; s < 2; s++) {
            int kb = s * 32;
            uint32_t a1f[4], a0f[4];
            ldsm4(a1f, uA1 + aoffr + kb);
            ldsm4(a0f, uA0 + aoffr + kb);
#pragma unroll
            for (int j = 0; j < 4; j++) {
                uint32_t b1f[4], b0f[4];
                ldsm4(b1f, uB1 + boffr + j * 16 * PADB + kb);
                ldsm4(b0f, uB0 + boffr + j * 16 * PADB + kb);
                imma16832(iH[2 * j],     a1f, &b1f[0]);
                imma16832(iH[2 * j + 1], a1f, &b1f[2]);
                imma16832(iX[2 * j],     a0f, &b1f[0]);
                imma16832(iX[2 * j + 1], a0f, &b1f[2]);
                imma16832(iX[2 * j],     a1f, &b0f[0]);
                imma16832(iX[2 * j + 1], a1f, &b0f[2]);
            }
        }
#pragma unroll
        for (int nf = 0; nf < 8; nf++)
#pragma unroll
            for (int e = 0; e < 4; e++)
                facc[nf][e] += 128.f * (float)iH[nf][e] + (float)iX[nf][e];
        __syncthreads();
    }

    // ---- epilogue: scale, store w2, BN2 stats
    float sc = g_scales[0] * g_scales[1] * (1.f / 128.f);
#pragma unroll
    for (int nf = 0; nf < 8; nf++) {
        int row = row0 + wm * 16 + g;
        int col = wn * 64 + nf * 8 + 2 * c4;
        float v0 = facc[nf][0] * sc, v1 = facc[nf][1] * sc;
        float v2 = facc[nf][2] * sc, v3 = facc[nf][3] * sc;
        *(float2*)(g_w2 + (size_t)row * 128 + col) = make_float2(v0, v1);
        *(float2*)(g_w2 + (size_t)(row + 8) * 128 + col) = make_float2(v2, v3);
        atomicAdd(&s_sum[col], v0 + v2);
        atomicAdd(&s_sq[col], v0 * v0 + v2 * v2);
        atomicAdd(&s_sum[col + 1], v1 + v3);
        atomicAdd(&s_sq[col + 1], v1 * v1 + v3 * v3);
    }
    __syncthreads();
    if (t < 128) {
        atomicAdd(&g_stat[256 + t], s_sum[t]);
        atomicAdd(&g_stat[384 + t], s_sq[t]);
    }
}

// ---------------- k_out: aff2 + leaky + softmax + weighted V sum ----------------
__global__ void k_out(const float* __restrict__ bv,
                      const float* __restrict__ g2, const float* __restrict__ b2,
                      float invc, float* __restrict__ out, int N) {
    int n = blockIdx.x;
    int c = threadIdx.x;
    __shared__ int sidx[KNN];
    if (c < KNN) sidx[c] = g_idx[n * KNN + c];
    __syncthreads();

    float mean2 = g_stat[256 + c] * invc;
    float var2  = g_stat[384 + c] * invc - mean2 * mean2;
    float sc2 = g2[c] * rsqrtf(var2 + EPS);
    float sh2 = b2[c] - mean2 * sc2;

    float tv[KNN];
    float m = -1e30f;
#pragma unroll
    for (int k = 0; k < KNN; k++) {
        float x = g_w2[(size_t)(n * KNN + k) * 128 + c];
        x = fmaf(x, sc2, sh2);
        x = x >= 0.f ? x : SLOPE * x;
        tv[k] = x;
        m = fmaxf(m, x);
    }
    float s = 0.f;
#pragma unroll
    for (int k = 0; k < KNN; k++) { float e = __expf(tv[k] - m); tv[k] = e; s += e; }
    float inv = 1.f / s;
    float b = bv[c];
    float acc = 0.f;
#pragma unroll
    for (int k = 0; k < KNN; k++) {
        float v = g_V[(size_t)sidx[k] * 128 + c] + b;
        acc = fmaf(tv[k] * inv, v, acc);
    }
    out[(size_t)n * 128 + c] = acc;
}

// ---------------- launch ----------------
extern "C" void kernel_launch(void* const* d_in, const int* in_sizes, int n_in,
                              void* d_out, int out_size) {
    const float* fea_i    = (const float*)d_in[0];
    const float* fea_last = (const float*)d_in[1];
    const float* xyz_i    = (const float*)d_in[2];
    const float* xyz_last = (const float*)d_in[3];
    const float* Wq = (const float*)d_in[5];
    const float* Wk = (const float*)d_in[7];
    const float* Wv = (const float*)d_in[9];
    const float* bv = (const float*)d_in[10];
    const float* g1 = (const float*)d_in[11];
    const float* b1 = (const float*)d_in[12];
    const float* Wl = (const float*)d_in[13];
    const float* g2 = (const float*)d_in[15];
    const float* b2 = (const float*)d_in[16];

    int N = in_sizes[0] / CIN;
    float invc = 1.0f / (float)(N * KNN);

    cudaFuncSetAttribute(k_qkv_gemm, cudaFuncAttributeMaxDynamicSharedMemorySize, QKV_SMEM);

    k_build<<<8, 1024>>>(xyz_i, Wq, Wk, Wv, Wl, g1, b1, N);         // idx 0

    dim3 gq(N / 128, 3);
    k_qkv_gemm<<<gq, 256, QKV_SMEM>>>(fea_i, fea_last);             // idx 1

    k_knn_warp<<<(N + 7) / 8, 256>>>(xyz_last, N);                  // idx 2 (knn + BN1 stats)

    k_w_gemm<<<N * KNN / 64, 256, W_SMEM>>>(g1, b1, invc);          // idx 3 (profiled)

    k_out<<<N, 128>>>(bv, g2, b2, invc, (float*)d_out, N);          // idx 4
}

// round 13
// speedup vs baseline: 1.1293x; 1.1293x over previous
#include <cuda_runtime.h>
#include <cuda_bf16.h>
#include <cstdint>

#define CIN 128
#define KNN 16
#define NMAX 8192
#define EPS 1e-5f
#define SLOPE 0.01f
#define GRID 8
#define NCELL (GRID * GRID * GRID)
#define CELLH (1.0f / GRID)
#define PADK 72   // bf16 stride per smem row; ldmatrix rows differ by 4 banks -> conflict-free

// ---------------- scratch (static device memory; no allocations) ----------------
__device__ int   g_idx[NMAX * KNN];
__device__ int   g_cid[NMAX];
__device__ int   g_cellstart[NCELL + 1];
__device__ __align__(16) float4 g_cellpts[NMAX];
__device__ __align__(16) float g_Q[NMAX * CIN];
__device__ __align__(16) float g_K[NMAX * CIN];
__device__ __align__(16) float g_V[NMAX * CIN];
__device__ __align__(16) float g_w2[(size_t)NMAX * KNN * CIN];
__device__ float g_stat[4 * CIN];   // [0:128)=sum1 [128:256)=sq1 [256:384)=sum2 [384:512)=sq2
__device__ __align__(16) __nv_bfloat16 g_Wbh[4 * CIN * CIN];  // Wq,Wk,Wv,Wl bf16-hi
__device__ __align__(16) __nv_bfloat16 g_Wbl[4 * CIN * CIN];  // Wq,Wk,Wv,Wl bf16-lo

__device__ __forceinline__ int cell1(float x) {
    int c = (int)(x * (float)GRID);
    return c < 0 ? 0 : (c > GRID - 1 ? GRID - 1 : c);
}

__device__ __forceinline__ uint32_t smem_u32(const void* p) {
    uint32_t a;
    asm("{ .reg .u64 t; cvta.to.shared.u64 t, %1; cvt.u32.u64 %0, t; }" : "=r"(a) : "l"(p));
    return a;
}
__device__ __forceinline__ void cp16(uint32_t dst, const void* src) {
    asm volatile("cp.async.cg.shared.global [%0], [%1], 16;" :: "r"(dst), "l"(src));
}
#define CP_COMMIT() asm volatile("cp.async.commit_group;")
#define CP_WAIT0()  asm volatile("cp.async.wait_group 0;" ::: "memory")

__device__ __forceinline__ void ldsm4(uint32_t* r, uint32_t addr) {
    asm volatile("ldmatrix.sync.aligned.m8n8.x4.shared.b16 {%0,%1,%2,%3}, [%4];"
        : "=r"(r[0]), "=r"(r[1]), "=r"(r[2]), "=r"(r[3]) : "r"(addr));
}

// fp32 -> (bf16 hi, bf16 lo) pair pack
__device__ __forceinline__ void split_pair(float x0, float x1, uint32_t& hp, uint32_t& lp) {
    __nv_bfloat16 h0 = __float2bfloat16(x0);
    __nv_bfloat16 h1 = __float2bfloat16(x1);
    __nv_bfloat16 l0 = __float2bfloat16(x0 - __bfloat162float(h0));
    __nv_bfloat16 l1 = __float2bfloat16(x1 - __bfloat162float(h1));
    hp = ((uint32_t)__bfloat16_as_ushort(h1) << 16) | __bfloat16_as_ushort(h0);
    lp = ((uint32_t)__bfloat16_as_ushort(l1) << 16) | __bfloat16_as_ushort(l0);
}

__device__ __forceinline__ void mma16816(float* d, const uint32_t* a, const uint32_t* b) {
    asm volatile(
        "mma.sync.aligned.m16n8k16.row.col.f32.bf16.bf16.f32 "
        "{%0,%1,%2,%3}, {%4,%5,%6,%7}, {%8,%9}, {%0,%1,%2,%3};"
        : "+f"(d[0]), "+f"(d[1]), "+f"(d[2]), "+f"(d[3])
        : "r"(a[0]), "r"(a[1]), "r"(a[2]), "r"(a[3]), "r"(b[0]), "r"(b[1]));
}

// ---------------- k_build: block 0 = grid build + stat zero, blocks 1..8 = weight presplit --
__global__ void __launch_bounds__(1024) k_build(
    const float* __restrict__ xyz_i,
    const float* __restrict__ Wq, const float* __restrict__ Wk,
    const float* __restrict__ Wv, const float* __restrict__ Wl, int N)
{
    int t = threadIdx.x;
    int b = blockIdx.x;

    if (b > 0) {
        uint32_t* oh = (uint32_t*)g_Wbh;
        uint32_t* ol = (uint32_t*)g_Wbl;
        int e0 = (b - 1) * 4096;
#pragma unroll
        for (int v = 0; v < 4; v++) {
            int e = e0 + v * 1024 + t;
            int m = e >> 13;
            int off = (e & 8191) * 2;
            const float* W = (m == 0) ? Wq : (m == 1 ? Wk : (m == 2 ? Wv : Wl));
            float2 x = *(const float2*)(W + off);
            uint32_t hp, lp;
            split_pair(x.x, x.y, hp, lp);
            oh[e] = hp;
            ol[e] = lp;
        }
        return;
    }

    __shared__ int scnt[NCELL];
    __shared__ int spre[NCELL];
    __shared__ int scur[NCELL];

    if (t < NCELL) scnt[t] = 0;
    if (t < 4 * CIN) g_stat[t] = 0.f;
    __syncthreads();

    for (int i = t; i < N; i += 1024) {
        float x = xyz_i[i * 3 + 0], y = xyz_i[i * 3 + 1], z = xyz_i[i * 3 + 2];
        int cid = (cell1(z) * GRID + cell1(y)) * GRID + cell1(x);
        g_cid[i] = cid;
        atomicAdd(&scnt[cid], 1);
    }
    __syncthreads();

    if (t < NCELL) spre[t] = scnt[t];
    __syncthreads();
    for (int o = 1; o < NCELL; o <<= 1) {
        int v = (t >= o && t < NCELL) ? spre[t - o] : 0;
        __syncthreads();
        if (t < NCELL) spre[t] += v;
        __syncthreads();
    }
    if (t < NCELL) {
        int excl = spre[t] - scnt[t];
        g_cellstart[t] = excl;
        scur[t] = excl;
    }
    if (t == NCELL - 1) g_cellstart[NCELL] = spre[NCELL - 1];
    __syncthreads();

    for (int i = t; i < N; i += 1024) {
        float x = xyz_i[i * 3 + 0], y = xyz_i[i * 3 + 1], z = xyz_i[i * 3 + 2];
        int slot = atomicAdd(&scur[g_cid[i]], 1);
        g_cellpts[slot] = make_float4(x, y, z, __int_as_float(i));
    }
}

// ---------------- serial fallback knn (exact, shell expansion) ----------------
__device__ void knn_serial(int q, float qx, float qy, float qz, int cx, int cy, int cz) {
    float bd[KNN];
    int   bi[KNN];
#pragma unroll
    for (int s = 0; s < KNN; s++) { bd[s] = 1e30f; bi[s] = -1; }
    float curmax = 1e30f;
    int maxslot = 0;
    for (int R = 0; R < GRID; R++) {
        int zlo = cz - R < 0 ? 0 : cz - R, zhi = cz + R > GRID - 1 ? GRID - 1 : cz + R;
        int ylo = cy - R < 0 ? 0 : cy - R, yhi = cy + R > GRID - 1 ? GRID - 1 : cy + R;
        int xlo = cx - R < 0 ? 0 : cx - R, xhi = cx + R > GRID - 1 ? GRID - 1 : cx + R;
        for (int zz = zlo; zz <= zhi; zz++) {
            int adz = zz - cz; adz = adz < 0 ? -adz : adz;
            for (int yy = ylo; yy <= yhi; yy++) {
                int ady = yy - cy; ady = ady < 0 ? -ady : ady;
                int rowmax = adz > ady ? adz : ady;
                for (int xx = xlo; xx <= xhi; xx++) {
                    int adx = xx - cx; adx = adx < 0 ? -adx : adx;
                    int cheb = rowmax > adx ? rowmax : adx;
                    if (cheb != R) continue;
                    int cellid = (zz * GRID + yy) * GRID + xx;
                    int s0 = g_cellstart[cellid];
                    int s1 = g_cellstart[cellid + 1];
                    for (int s = s0; s < s1; s++) {
                        float4 p = g_cellpts[s];
                        float dx = qx - p.x, dy = qy - p.y, dz = qz - p.z;
                        float d2 = fmaf(dx, dx, fmaf(dy, dy, dz * dz));
                        if (d2 < curmax) {
                            int j = __float_as_int(p.w);
#pragma unroll
                            for (int u = 0; u < KNN; u++)
                                if (u == maxslot) { bd[u] = d2; bi[u] = j; }
                            curmax = -1.f;
#pragma unroll
                            for (int u = 0; u < KNN; u++)
                                if (bd[u] > curmax) { curmax = bd[u]; maxslot = u; }
                        }
                    }
                }
            }
        }
        float reach = (float)R * CELLH;
        if (curmax <= reach * reach) break;
    }
#pragma unroll
    for (int s = 0; s < KNN; s++) g_idx[q * KNN + s] = bi[s];
}

// ---------------- warp-per-query knn + fused BN1 stats ----------------
__global__ void __launch_bounds__(256) k_knn_warp(const float* __restrict__ xyz_last, int N) {
    __shared__ int s_pre[8][12];
    __shared__ int s_s0[8][12];
    __shared__ float s_sum[128], s_sq[128];
    int w = threadIdx.x >> 5;
    int lid = threadIdx.x & 31;
    int q = (blockIdx.x * 256 + threadIdx.x) >> 5;

    if (threadIdx.x < 128) { s_sum[threadIdx.x] = 0.f; s_sq[threadIdx.x] = 0.f; }
    __syncthreads();

    bool valid = (q < N);
    if (valid) {
        float qx = xyz_last[q * 3 + 0];
        float qy = xyz_last[q * 3 + 1];
        float qz = xyz_last[q * 3 + 2];
        int cx = cell1(qx), cy = cell1(qy), cz = cell1(qz);

        int zlo = cz - 1 < 0 ? 0 : cz - 1, zhi = cz + 1 > GRID - 1 ? GRID - 1 : cz + 1;
        int ylo = cy - 1 < 0 ? 0 : cy - 1, yhi = cy + 1 > GRID - 1 ? GRID - 1 : cy + 1;
        int xlo = cx - 1 < 0 ? 0 : cx - 1, xhi = cx + 1 > GRID - 1 ? GRID - 1 : cx + 1;
        int ny = yhi - ylo + 1;
        int nrows = (zhi - zlo + 1) * ny;   // <= 9

        int s0 = 0, len = 0;
        if (lid < nrows) {
            int zz = zlo + lid / ny;
            int yy = ylo + lid % ny;
            int cbase = (zz * GRID + yy) * GRID;
            s0 = g_cellstart[cbase + xlo];
            len = g_cellstart[cbase + xhi + 1] - s0;
        }
        int pre = len;
#pragma unroll
        for (int o = 1; o < 32; o <<= 1) {
            int v = __shfl_up_sync(0xFFFFFFFFu, pre, o);
            if (lid >= o) pre += v;
        }
        int T = __shfl_sync(0xFFFFFFFFu, pre, 31);
        int myStart = pre - len;

        if (lid < 12) { s_pre[w][lid] = 0x7FFFFFFF; s_s0[w][lid] = 0; }
        __syncwarp();
        if (lid <= nrows && lid < 10) s_pre[w][lid] = myStart;
        if (lid < nrows) s_s0[w][lid] = s0;
        __syncwarp();

        float bd[KNN];
        int   bi[KNN];
#pragma unroll
        for (int s = 0; s < KNN; s++) { bd[s] = 1e30f; bi[s] = -1; }
        float curmax = 1e30f;
        int maxslot = 0;

        int niter = (T + 31) >> 5;
        for (int it = 0; it < niter; it++) {
            int c = it * 32 + lid;
            if (c < T) {
                int j = 0;
#pragma unroll
                for (int i = 1; i <= 9; i++) j += (c >= s_pre[w][i]) ? 1 : 0;
                int slot = s_s0[w][j] + (c - s_pre[w][j]);
                float4 p = g_cellpts[slot];
                float dx = qx - p.x, dy = qy - p.y, dz = qz - p.z;
                float d2 = fmaf(dx, dx, fmaf(dy, dy, dz * dz));
                if (d2 < curmax) {
                    int ji = __float_as_int(p.w);
#pragma unroll
                    for (int u = 0; u < KNN; u++)
                        if (u == maxslot) { bd[u] = d2; bi[u] = ji; }
                    curmax = -1.f;
#pragma unroll
                    for (int u = 0; u < KNN; u++)
                        if (bd[u] > curmax) { curmax = bd[u]; maxslot = u; }
                }
            }
        }

        float lmin = 1e30f;
        int lslot = 0;
#pragma unroll
        for (int s = 0; s < KNN; s++)
            if (bd[s] < lmin) { lmin = bd[s]; lslot = s; }

        float d16 = 0.f;
        int myres = -1;
        for (int r = 0; r < KNN; r++) {
            float v = lmin;
            int wl = lid;
#pragma unroll
            for (int o = 16; o; o >>= 1) {
                float ov = __shfl_xor_sync(0xFFFFFFFFu, v, o);
                int owl = __shfl_xor_sync(0xFFFFFFFFu, wl, o);
                if (ov < v || (ov == v && owl < wl)) { v = ov; wl = owl; }
            }
            int myidx = -1;
#pragma unroll
            for (int s = 0; s < KNN; s++)
                if (s == lslot) myidx = bi[s];
            int wi = __shfl_sync(0xFFFFFFFFu, myidx, wl);
            d16 = v;
            if (lid == r) myres = wi;
            if (lid == wl) {
#pragma unroll
                for (int s = 0; s < KNN; s++)
                    if (s == lslot) bd[s] = 1e30f;
                lmin = 1e30f; lslot = 0;
#pragma unroll
                for (int s = 0; s < KNN; s++)
                    if (bd[s] < lmin) { lmin = bd[s]; lslot = s; }
            }
        }

        if (d16 <= CELLH * CELLH) {
            if (lid < KNN) g_idx[q * KNN + lid] = myres;
        } else {
            if (lid == 0) knn_serial(q, qx, qy, qz, cx, cy, cz);
        }
        __syncwarp();

        // fused BN1 stats: lane owns 4 channels of query q
        {
            int cb = lid * 4;
            float4 Qv = *(const float4*)(g_Q + (size_t)q * 128 + cb);
            float S0 = 0.f, S1 = 0.f, S2 = 0.f, S3 = 0.f;
            float T0 = 0.f, T1 = 0.f, T2 = 0.f, T3 = 0.f;
#pragma unroll
            for (int k = 0; k < KNN; k++) {
                int j = g_idx[q * KNN + k];
                float4 kv = *(const float4*)(g_K + (size_t)j * 128 + cb);
                S0 += kv.x; T0 = fmaf(kv.x, kv.x, T0);
                S1 += kv.y; T1 = fmaf(kv.y, kv.y, T1);
                S2 += kv.z; T2 = fmaf(kv.z, kv.z, T2);
                S3 += kv.w; T3 = fmaf(kv.w, kv.w, T3);
            }
            atomicAdd(&s_sum[cb + 0], 16.f * Qv.x - S0);
            atomicAdd(&s_sum[cb + 1], 16.f * Qv.y - S1);
            atomicAdd(&s_sum[cb + 2], 16.f * Qv.z - S2);
            atomicAdd(&s_sum[cb + 3], 16.f * Qv.w - S3);
            atomicAdd(&s_sq[cb + 0], fmaf(16.f * Qv.x, Qv.x, fmaf(-2.f * Qv.x, S0, T0)));
            atomicAdd(&s_sq[cb + 1], fmaf(16.f * Qv.y, Qv.y, fmaf(-2.f * Qv.y, S1, T1)));
            atomicAdd(&s_sq[cb + 2], fmaf(16.f * Qv.z, Qv.z, fmaf(-2.f * Qv.z, S2, T2)));
            atomicAdd(&s_sq[cb + 3], fmaf(16.f * Qv.w, Qv.w, fmaf(-2.f * Qv.w, S3, T3)));
        }
    }
    __syncthreads();
    if (threadIdx.x < 128) {
        atomicAdd(&g_stat[threadIdx.x], s_sum[threadIdx.x]);
        atomicAdd(&g_stat[128 + threadIdx.x], s_sq[threadIdx.x]);
    }
}

// ---------------- mma.sync GEMM, K-tiled (BK=64), ldmatrix frags, coalesced gather --
#define TILEB (128 * PADK * 2)
#define SM_AHI 0
#define SM_ALO TILEB
#define SM_BHI (2 * TILEB)
#define SM_BLO (3 * TILEB)
#define SM_AFF (4 * TILEB)                // 256 floats
#define SM_SUM (SM_AFF + 1024)
#define SM_SQ  (SM_SUM + 512)
#define SMEM_TOTAL (SM_SQ + 512)          // ~74 KB -> 2 blocks/SM (reg-limited)

__global__ void __launch_bounds__(256, 2) k_mma_gemm(
    int mode,
    const float* __restrict__ fea_i, const float* __restrict__ fea_last,
    const float* __restrict__ g1, const float* __restrict__ b1, float invc)
{
    extern __shared__ char smem[];
    int t = threadIdx.x;
    int lane = t & 31, wid = t >> 5;
    int g = lane >> 2, c4 = lane & 3;
    int wm = wid & 3, wn = wid >> 2;
    int row0 = blockIdx.x * 128;

    char* Ah = smem + SM_AHI;
    char* Al = smem + SM_ALO;
    char* Bh = smem + SM_BHI;
    char* Bl = smem + SM_BLO;
    float* s_aff = (float*)(smem + SM_AFF);
    float* s_sum = (float*)(smem + SM_SUM);
    float* s_sq  = (float*)(smem + SM_SQ);

    int wsel;
    float* C;
    const float* Asrc = nullptr;
    if (mode == 0) {
        wsel = blockIdx.y;
        Asrc = (wsel == 0) ? fea_last : fea_i;
        C = (wsel == 0) ? g_Q : (wsel == 1 ? g_K : g_V);
    } else {
        wsel = 3;
        C = g_w2;
    }

    if (mode == 1) {
        if (t < 128) {
            float mean = g_stat[t] * invc;
            float var  = g_stat[128 + t] * invc - mean * mean;
            float sc = g1[t] * rsqrtf(var + EPS);
            s_aff[t] = sc;
            s_aff[128 + t] = b1[t] - mean * sc;
            s_sum[t] = 0.f;
            s_sq[t]  = 0.f;
        }
        __syncthreads();
    }

    float acc[2][8][4];
#pragma unroll
    for (int mf = 0; mf < 2; mf++)
#pragma unroll
        for (int nf = 0; nf < 8; nf++)
#pragma unroll
            for (int e = 0; e < 4; e++) acc[mf][nf][e] = 0.f;

    int pr = t >> 1;
    int pch = (t & 1) * 32;

    const __nv_bfloat16* Wsh = g_Wbh + wsel * CIN * CIN;
    const __nv_bfloat16* Wsl = g_Wbl + wsel * CIN * CIN;

    int quad = lane >> 3, lr = lane & 7;
    int aoffe = (wm * 32 + (quad & 1) * 8 + lr) * PADK + (quad >> 1) * 8;
    int boffe = (wn * 64 + (quad >> 1) * 8 + lr) * PADK + (quad & 1) * 8;
    uint32_t uAh = smem_u32(Ah), uAl = smem_u32(Al);
    uint32_t uBh = smem_u32(Bh), uBl = smem_u32(Bl);

#pragma unroll 1
    for (int pass = 0; pass < 2; pass++) {
        int kk0 = pass * 64;
        // ---- B slice via cp.async (overlaps A prep)
        {
            const __nv_bfloat16* sh = Wsh + pr * 128 + kk0 + pch;
            const __nv_bfloat16* sl = Wsl + pr * 128 + kk0 + pch;
            uint32_t dh = smem_u32(Bh + (pr * PADK + pch) * 2);
            uint32_t dl = smem_u32(Bl + (pr * PADK + pch) * 2);
#pragma unroll
            for (int c = 0; c < 4; c++) {
                cp16(dh + c * 16, sh + c * 8);
                cp16(dl + c * 16, sl + c * 8);
            }
            CP_COMMIT();
        }
        // ---- A prep: warp-per-row coalesced; mode 1 hoists the (warp-invariant) Q row
        {
            int cg = kk0 + 2 * lane;
            float sc0 = 0.f, sc1 = 0.f, sh0 = 0.f, sh1 = 0.f;
            float2 qv = make_float2(0.f, 0.f);
            if (mode == 1) {
                sc0 = s_aff[cg];       sc1 = s_aff[cg + 1];
                sh0 = s_aff[128 + cg]; sh1 = s_aff[128 + cg + 1];
                int n = (row0 >> 4) + wid;    // all 16 rows of this warp share query n
                qv = *(const float2*)(g_Q + (size_t)n * 128 + cg);
            }
#pragma unroll
            for (int r = 0; r < 16; r++) {
                int row = wid * 16 + r;
                float x0, x1;
                if (mode == 0) {
                    float2 av = *(const float2*)(Asrc + (size_t)(row0 + row) * 128 + cg);
                    x0 = av.x; x1 = av.y;
                } else {
                    int j = g_idx[row0 + row];    // warp-uniform broadcast
                    float2 kv = *(const float2*)(g_K + (size_t)j * 128 + cg);
                    x0 = fmaf(qv.x - kv.x, sc0, sh0);
                    x1 = fmaf(qv.y - kv.y, sc1, sh1);
                    x0 = x0 >= 0.f ? x0 : SLOPE * x0;
                    x1 = x1 >= 0.f ? x1 : SLOPE * x1;
                }
                uint32_t hp, lp;
                split_pair(x0, x1, hp, lp);
                int off = (row * PADK + 2 * lane) * 2;
                *(uint32_t*)(Ah + off) = hp;
                *(uint32_t*)(Al + off) = lp;
            }
        }
        CP_WAIT0();
        __syncthreads();

        // ---- 4 K-steps of 16, fragments via ldmatrix.x4
#pragma unroll
        for (int s = 0; s < 4; s++) {
            int ke = s * 16;
            uint32_t ah[8], al[8], bh[16], bl[16];
            ldsm4(&ah[0], uAh + (aoffe + ke) * 2);
            ldsm4(&ah[4], uAh + (aoffe + 16 * PADK + ke) * 2);
            ldsm4(&al[0], uAl + (aoffe + ke) * 2);
            ldsm4(&al[4], uAl + (aoffe + 16 * PADK + ke) * 2);
#pragma unroll
            for (int j = 0; j < 4; j++) {
                ldsm4(&bh[4 * j], uBh + (boffe + j * 16 * PADK + ke) * 2);
                ldsm4(&bl[4 * j], uBl + (boffe + j * 16 * PADK + ke) * 2);
            }
#pragma unroll
            for (int mf = 0; mf < 2; mf++)
#pragma unroll
                for (int nf = 0; nf < 8; nf++) {
                    mma16816(acc[mf][nf], &ah[4 * mf], &bh[2 * nf]);
                    mma16816(acc[mf][nf], &al[4 * mf], &bh[2 * nf]);
                    mma16816(acc[mf][nf], &ah[4 * mf], &bl[2 * nf]);
                }
        }
        __syncthreads();
    }

    // ---- epilogue
#pragma unroll
    for (int mf = 0; mf < 2; mf++)
#pragma unroll
        for (int nf = 0; nf < 8; nf++) {
            int row = row0 + wm * 32 + mf * 16 + g;
            int col = wn * 64 + nf * 8 + 2 * c4;
            *(float2*)(C + (size_t)row * 128 + col) =
                make_float2(acc[mf][nf][0], acc[mf][nf][1]);
            *(float2*)(C + (size_t)(row + 8) * 128 + col) =
                make_float2(acc[mf][nf][2], acc[mf][nf][3]);
        }

    if (mode == 1) {
#pragma unroll
        for (int nf = 0; nf < 8; nf++) {
            int col = wn * 64 + nf * 8 + 2 * c4;
            float v00 = acc[0][nf][0], v02 = acc[0][nf][2];
            float v10 = acc[1][nf][0], v12 = acc[1][nf][2];
            atomicAdd(&s_sum[col], v00 + v02 + v10 + v12);
            atomicAdd(&s_sq[col], v00 * v00 + v02 * v02 + v10 * v10 + v12 * v12);
            float v01 = acc[0][nf][1], v03 = acc[0][nf][3];
            float v11 = acc[1][nf][1], v13 = acc[1][nf][3];
            atomicAdd(&s_sum[col + 1], v01 + v03 + v11 + v13);
            atomicAdd(&s_sq[col + 1], v01 * v01 + v03 * v03 + v11 * v11 + v13 * v13);
        }
        __syncthreads();
        if (t < 128) {
            atomicAdd(&g_stat[256 + t], s_sum[t]);
            atomicAdd(&g_stat[384 + t], s_sq[t]);
        }
    }
}

// ---------------- k_out: aff2 + leaky + softmax + weighted V sum ----------------
__global__ void k_out(const float* __restrict__ bv,
                      const float* __restrict__ g2, const float* __restrict__ b2,
                      float invc, float* __restrict__ out, int N) {
    int n = blockIdx.x;
    int c = threadIdx.x;
    __shared__ int sidx[KNN];
    if (c < KNN) sidx[c] = g_idx[n * KNN + c];
    __syncthreads();

    float mean2 = g_stat[256 + c] * invc;
    float var2  = g_stat[384 + c] * invc - mean2 * mean2;
    float sc2 = g2[c] * rsqrtf(var2 + EPS);
    float sh2 = b2[c] - mean2 * sc2;

    float tv[KNN];
    float m = -1e30f;
#pragma unroll
    for (int k = 0; k < KNN; k++) {
        float x = g_w2[(size_t)(n * KNN + k) * 128 + c];
        x = fmaf(x, sc2, sh2);
        x = x >= 0.f ? x : SLOPE * x;
        tv[k] = x;
        m = fmaxf(m, x);
    }
    float s = 0.f;
#pragma unroll
    for (int k = 0; k < KNN; k++) { float e = __expf(tv[k] - m); tv[k] = e; s += e; }
    float inv = 1.f / s;
    float b = bv[c];
    float acc = 0.f;
#pragma unroll
    for (int k = 0; k < KNN; k++) {
        float v = g_V[(size_t)sidx[k] * 128 + c] + b;
        acc = fmaf(tv[k] * inv, v, acc);
    }
    out[(size_t)n * 128 + c] = acc;
}

// ---------------- launch ----------------
extern "C" void kernel_launch(void* const* d_in, const int* in_sizes, int n_in,
                              void* d_out, int out_size) {
    const float* fea_i    = (const float*)d_in[0];
    const float* fea_last = (const float*)d_in[1];
    const float* xyz_i    = (const float*)d_in[2];
    const float* xyz_last = (const float*)d_in[3];
    const float* Wq = (const float*)d_in[5];
    const float* Wk = (const float*)d_in[7];
    const float* Wv = (const float*)d_in[9];
    const float* bv = (const float*)d_in[10];
    const float* g1 = (const float*)d_in[11];
    const float* b1 = (const float*)d_in[12];
    const float* Wl = (const float*)d_in[13];
    const float* g2 = (const float*)d_in[15];
    const float* b2 = (const float*)d_in[16];

    int N = in_sizes[0] / CIN;
    float invc = 1.0f / (float)(N * KNN);

    cudaFuncSetAttribute(k_mma_gemm, cudaFuncAttributeMaxDynamicSharedMemorySize, SMEM_TOTAL);

    k_build<<<9, 1024>>>(xyz_i, Wq, Wk, Wv, Wl, N);                 // idx 0

    dim3 gq(N / 128, 3);
    k_mma_gemm<<<gq, 256, SMEM_TOTAL>>>(0, fea_i, fea_last, g1, b1, invc);  // idx 1

    k_knn_warp<<<(N + 7) / 8, 256>>>(xyz_last, N);                  // idx 2 (knn + BN1 stats)

    k_mma_gemm<<<N * KNN / 128, 256, SMEM_TOTAL>>>(1, fea_i, fea_last, g1, b1, invc); // idx 3 (profiled)

    k_out<<<N, 128>>>(bv, g2, b2, invc, (float*)d_out, N);          // idx 4
}

// round 14
// speedup vs baseline: 1.1296x; 1.0003x over previous
#include <cuda_runtime.h>
#include <cuda_bf16.h>
#include <cstdint>

#define CIN 128
#define KNN 16
#define NMAX 8192
#define EPS 1e-5f
#define SLOPE 0.01f
#define GRID 8
#define NCELL (GRID * GRID * GRID)
#define CELLH (1.0f / GRID)
#define PADK 72   // bf16 stride per smem row; ldmatrix rows differ by 4 banks -> conflict-free

// ---------------- scratch (static device memory; no allocations) ----------------
__device__ int   g_idx[NMAX * KNN];
__device__ int   g_cid[NMAX];
__device__ int   g_cellstart[NCELL + 1];
__device__ __align__(16) float4 g_cellpts[NMAX];
__device__ __align__(16) float g_Q[NMAX * CIN];
__device__ __align__(16) float g_K[NMAX * CIN];
__device__ __align__(16) float g_V[NMAX * CIN];
__device__ __align__(16) float g_w2[(size_t)NMAX * KNN * CIN];
__device__ float g_stat[4 * CIN];   // [0:128)=sum1 [128:256)=sq1 [256:384)=sum2 [384:512)=sq2
__device__ __align__(16) __nv_bfloat16 g_Wbh[4 * CIN * CIN];  // Wq,Wk,Wv,Wl bf16-hi
__device__ __align__(16) __nv_bfloat16 g_Wbl[4 * CIN * CIN];  // Wq,Wk,Wv,Wl bf16-lo

__device__ __forceinline__ int cell1(float x) {
    int c = (int)(x * (float)GRID);
    return c < 0 ? 0 : (c > GRID - 1 ? GRID - 1 : c);
}

__device__ __forceinline__ uint32_t smem_u32(const void* p) {
    uint32_t a;
    asm("{ .reg .u64 t; cvta.to.shared.u64 t, %1; cvt.u32.u64 %0, t; }" : "=r"(a) : "l"(p));
    return a;
}
__device__ __forceinline__ void cp16(uint32_t dst, const void* src) {
    asm volatile("cp.async.cg.shared.global [%0], [%1], 16;" :: "r"(dst), "l"(src));
}
#define CP_COMMIT() asm volatile("cp.async.commit_group;")
#define CP_WAIT0()  asm volatile("cp.async.wait_group 0;" ::: "memory")

__device__ __forceinline__ void ldsm4(uint32_t* r, uint32_t addr) {
    asm volatile("ldmatrix.sync.aligned.m8n8.x4.shared.b16 {%0,%1,%2,%3}, [%4];"
        : "=r"(r[0]), "=r"(r[1]), "=r"(r[2]), "=r"(r[3]) : "r"(addr));
}

// fp32 -> (bf16 hi, bf16 lo) pair pack
__device__ __forceinline__ void split_pair(float x0, float x1, uint32_t& hp, uint32_t& lp) {
    __nv_bfloat16 h0 = __float2bfloat16(x0);
    __nv_bfloat16 h1 = __float2bfloat16(x1);
    __nv_bfloat16 l0 = __float2bfloat16(x0 - __bfloat162float(h0));
    __nv_bfloat16 l1 = __float2bfloat16(x1 - __bfloat162float(h1));
    hp = ((uint32_t)__bfloat16_as_ushort(h1) << 16) | __bfloat16_as_ushort(h0);
    lp = ((uint32_t)__bfloat16_as_ushort(l1) << 16) | __bfloat16_as_ushort(l0);
}

__device__ __forceinline__ void mma16816(float* d, const uint32_t* a, const uint32_t* b) {
    asm volatile(
        "mma.sync.aligned.m16n8k16.row.col.f32.bf16.bf16.f32 "
        "{%0,%1,%2,%3}, {%4,%5,%6,%7}, {%8,%9}, {%0,%1,%2,%3};"
        : "+f"(d[0]), "+f"(d[1]), "+f"(d[2]), "+f"(d[3])
        : "r"(a[0]), "r"(a[1]), "r"(a[2]), "r"(a[3]), "r"(b[0]), "r"(b[1]));
}

// ---------------- k_build: block 0 = grid build + stat zero, blocks 1..8 = weight presplit --
__global__ void __launch_bounds__(1024) k_build(
    const float* __restrict__ xyz_i,
    const float* __restrict__ Wq, const float* __restrict__ Wk,
    const float* __restrict__ Wv, const float* __restrict__ Wl, int N)
{
    int t = threadIdx.x;
    int b = blockIdx.x;

    if (b > 0) {
        uint32_t* oh = (uint32_t*)g_Wbh;
        uint32_t* ol = (uint32_t*)g_Wbl;
        int e0 = (b - 1) * 4096;
#pragma unroll
        for (int v = 0; v < 4; v++) {
            int e = e0 + v * 1024 + t;
            int m = e >> 13;
            int off = (e & 8191) * 2;
            const float* W = (m == 0) ? Wq : (m == 1 ? Wk : (m == 2 ? Wv : Wl));
            float2 x = *(const float2*)(W + off);
            uint32_t hp, lp;
            split_pair(x.x, x.y, hp, lp);
            oh[e] = hp;
            ol[e] = lp;
        }
        return;
    }

    __shared__ int scnt[NCELL];
    __shared__ int spre[NCELL];
    __shared__ int scur[NCELL];

    if (t < NCELL) scnt[t] = 0;
    if (t < 4 * CIN) g_stat[t] = 0.f;
    __syncthreads();

    for (int i = t; i < N; i += 1024) {
        float x = xyz_i[i * 3 + 0], y = xyz_i[i * 3 + 1], z = xyz_i[i * 3 + 2];
        int cid = (cell1(z) * GRID + cell1(y)) * GRID + cell1(x);
        g_cid[i] = cid;
        atomicAdd(&scnt[cid], 1);
    }
    __syncthreads();

    if (t < NCELL) spre[t] = scnt[t];
    __syncthreads();
    for (int o = 1; o < NCELL; o <<= 1) {
        int v = (t >= o && t < NCELL) ? spre[t - o] : 0;
        __syncthreads();
        if (t < NCELL) spre[t] += v;
        __syncthreads();
    }
    if (t < NCELL) {
        int excl = spre[t] - scnt[t];
        g_cellstart[t] = excl;
        scur[t] = excl;
    }
    if (t == NCELL - 1) g_cellstart[NCELL] = spre[NCELL - 1];
    __syncthreads();

    for (int i = t; i < N; i += 1024) {
        float x = xyz_i[i * 3 + 0], y = xyz_i[i * 3 + 1], z = xyz_i[i * 3 + 2];
        int slot = atomicAdd(&scur[g_cid[i]], 1);
        g_cellpts[slot] = make_float4(x, y, z, __int_as_float(i));
    }
}

// ---------------- serial fallback knn (exact, shell expansion) ----------------
__device__ void knn_serial(int q, float qx, float qy, float qz, int cx, int cy, int cz) {
    float bd[KNN];
    int   bi[KNN];
#pragma unroll
    for (int s = 0; s < KNN; s++) { bd[s] = 1e30f; bi[s] = -1; }
    float curmax = 1e30f;
    int maxslot = 0;
    for (int R = 0; R < GRID; R++) {
        int zlo = cz - R < 0 ? 0 : cz - R, zhi = cz + R > GRID - 1 ? GRID - 1 : cz + R;
        int ylo = cy - R < 0 ? 0 : cy - R, yhi = cy + R > GRID - 1 ? GRID - 1 : cy + R;
        int xlo = cx - R < 0 ? 0 : cx - R, xhi = cx + R > GRID - 1 ? GRID - 1 : cx + R;
        for (int zz = zlo; zz <= zhi; zz++) {
            int adz = zz - cz; adz = adz < 0 ? -adz : adz;
            for (int yy = ylo; yy <= yhi; yy++) {
                int ady = yy - cy; ady = ady < 0 ? -ady : ady;
                int rowmax = adz > ady ? adz : ady;
                for (int xx = xlo; xx <= xhi; xx++) {
                    int adx = xx - cx; adx = adx < 0 ? -adx : adx;
                    int cheb = rowmax > adx ? rowmax : adx;
                    if (cheb != R) continue;
                    int cellid = (zz * GRID + yy) * GRID + xx;
                    int s0 = g_cellstart[cellid];
                    int s1 = g_cellstart[cellid + 1];
                    for (int s = s0; s < s1; s++) {
                        float4 p = g_cellpts[s];
                        float dx = qx - p.x, dy = qy - p.y, dz = qz - p.z;
                        float d2 = fmaf(dx, dx, fmaf(dy, dy, dz * dz));
                        if (d2 < curmax) {
                            int j = __float_as_int(p.w);
#pragma unroll
                            for (int u = 0; u < KNN; u++)
                                if (u == maxslot) { bd[u] = d2; bi[u] = j; }
                            curmax = -1.f;
#pragma unroll
                            for (int u = 0; u < KNN; u++)
                                if (bd[u] > curmax) { curmax = bd[u]; maxslot = u; }
                        }
                    }
                }
            }
        }
        float reach = (float)R * CELLH;
        if (curmax <= reach * reach) break;
    }
#pragma unroll
    for (int s = 0; s < KNN; s++) g_idx[q * KNN + s] = bi[s];
}

// ---------------- warp-per-query knn + fused BN1 stats ----------------
__global__ void __launch_bounds__(256) k_knn_warp(const float* __restrict__ xyz_last, int N) {
    __shared__ int s_pre[8][12];
    __shared__ int s_s0[8][12];
    __shared__ float s_sum[128], s_sq[128];
    int w = threadIdx.x >> 5;
    int lid = threadIdx.x & 31;
    int q = (blockIdx.x * 256 + threadIdx.x) >> 5;

    if (threadIdx.x < 128) { s_sum[threadIdx.x] = 0.f; s_sq[threadIdx.x] = 0.f; }
    __syncthreads();

    bool valid = (q < N);
    if (valid) {
        float qx = xyz_last[q * 3 + 0];
        float qy = xyz_last[q * 3 + 1];
        float qz = xyz_last[q * 3 + 2];
        int cx = cell1(qx), cy = cell1(qy), cz = cell1(qz);

        int zlo = cz - 1 < 0 ? 0 : cz - 1, zhi = cz + 1 > GRID - 1 ? GRID - 1 : cz + 1;
        int ylo = cy - 1 < 0 ? 0 : cy - 1, yhi = cy + 1 > GRID - 1 ? GRID - 1 : cy + 1;
        int xlo = cx - 1 < 0 ? 0 : cx - 1, xhi = cx + 1 > GRID - 1 ? GRID - 1 : cx + 1;
        int ny = yhi - ylo + 1;
        int nrows = (zhi - zlo + 1) * ny;   // <= 9

        int s0 = 0, len = 0;
        if (lid < nrows) {
            int zz = zlo + lid / ny;
            int yy = ylo + lid % ny;
            int cbase = (zz * GRID + yy) * GRID;
            s0 = g_cellstart[cbase + xlo];
            len = g_cellstart[cbase + xhi + 1] - s0;
        }
        int pre = len;
#pragma unroll
        for (int o = 1; o < 32; o <<= 1) {
            int v = __shfl_up_sync(0xFFFFFFFFu, pre, o);
            if (lid >= o) pre += v;
        }
        int T = __shfl_sync(0xFFFFFFFFu, pre, 31);
        int myStart = pre - len;

        if (lid < 12) { s_pre[w][lid] = 0x7FFFFFFF; s_s0[w][lid] = 0; }
        __syncwarp();
        if (lid <= nrows && lid < 10) s_pre[w][lid] = myStart;
        if (lid < nrows) s_s0[w][lid] = s0;
        __syncwarp();

        float bd[KNN];
        int   bi[KNN];
#pragma unroll
        for (int s = 0; s < KNN; s++) { bd[s] = 1e30f; bi[s] = -1; }
        float curmax = 1e30f;
        int maxslot = 0;

        int niter = (T + 31) >> 5;
        for (int it = 0; it < niter; it++) {
            int c = it * 32 + lid;
            if (c < T) {
                int j = 0;
#pragma unroll
                for (int i = 1; i <= 9; i++) j += (c >= s_pre[w][i]) ? 1 : 0;
                int slot = s_s0[w][j] + (c - s_pre[w][j]);
                float4 p = g_cellpts[slot];
                float dx = qx - p.x, dy = qy - p.y, dz = qz - p.z;
                float d2 = fmaf(dx, dx, fmaf(dy, dy, dz * dz));
                if (d2 < curmax) {
                    int ji = __float_as_int(p.w);
#pragma unroll
                    for (int u = 0; u < KNN; u++)
                        if (u == maxslot) { bd[u] = d2; bi[u] = ji; }
                    curmax = -1.f;
#pragma unroll
                    for (int u = 0; u < KNN; u++)
                        if (bd[u] > curmax) { curmax = bd[u]; maxslot = u; }
                }
            }
        }

        float lmin = 1e30f;
        int lslot = 0;
#pragma unroll
        for (int s = 0; s < KNN; s++)
            if (bd[s] < lmin) { lmin = bd[s]; lslot = s; }

        float d16 = 0.f;
        int myres = -1;
        for (int r = 0; r < KNN; r++) {
            float v = lmin;
            int wl = lid;
#pragma unroll
            for (int o = 16; o; o >>= 1) {
                float ov = __shfl_xor_sync(0xFFFFFFFFu, v, o);
                int owl = __shfl_xor_sync(0xFFFFFFFFu, wl, o);
                if (ov < v || (ov == v && owl < wl)) { v = ov; wl = owl; }
            }
            int myidx = -1;
#pragma unroll
            for (int s = 0; s < KNN; s++)
                if (s == lslot) myidx = bi[s];
            int wi = __shfl_sync(0xFFFFFFFFu, myidx, wl);
            d16 = v;
            if (lid == r) myres = wi;
            if (lid == wl) {
#pragma unroll
                for (int s = 0; s < KNN; s++)
                    if (s == lslot) bd[s] = 1e30f;
                lmin = 1e30f; lslot = 0;
#pragma unroll
                for (int s = 0; s < KNN; s++)
                    if (bd[s] < lmin) { lmin = bd[s]; lslot = s; }
            }
        }

        if (d16 <= CELLH * CELLH) {
            if (lid < KNN) g_idx[q * KNN + lid] = myres;
        } else {
            if (lid == 0) knn_serial(q, qx, qy, qz, cx, cy, cz);
        }
        __syncwarp();

        // fused BN1 stats: lane owns 4 channels of query q
        {
            int cb = lid * 4;
            float4 Qv = *(const float4*)(g_Q + (size_t)q * 128 + cb);
            float S0 = 0.f, S1 = 0.f, S2 = 0.f, S3 = 0.f;
            float T0 = 0.f, T1 = 0.f, T2 = 0.f, T3 = 0.f;
#pragma unroll
            for (int k = 0; k < KNN; k++) {
                int j = g_idx[q * KNN + k];
                float4 kv = *(const float4*)(g_K + (size_t)j * 128 + cb);
                S0 += kv.x; T0 = fmaf(kv.x, kv.x, T0);
                S1 += kv.y; T1 = fmaf(kv.y, kv.y, T1);
                S2 += kv.z; T2 = fmaf(kv.z, kv.z, T2);
                S3 += kv.w; T3 = fmaf(kv.w, kv.w, T3);
            }
            atomicAdd(&s_sum[cb + 0], 16.f * Qv.x - S0);
            atomicAdd(&s_sum[cb + 1], 16.f * Qv.y - S1);
            atomicAdd(&s_sum[cb + 2], 16.f * Qv.z - S2);
            atomicAdd(&s_sum[cb + 3], 16.f * Qv.w - S3);
            atomicAdd(&s_sq[cb + 0], fmaf(16.f * Qv.x, Qv.x, fmaf(-2.f * Qv.x, S0, T0)));
            atomicAdd(&s_sq[cb + 1], fmaf(16.f * Qv.y, Qv.y, fmaf(-2.f * Qv.y, S1, T1)));
            atomicAdd(&s_sq[cb + 2], fmaf(16.f * Qv.z, Qv.z, fmaf(-2.f * Qv.z, S2, T2)));
            atomicAdd(&s_sq[cb + 3], fmaf(16.f * Qv.w, Qv.w, fmaf(-2.f * Qv.w, S3, T3)));
        }
    }
    __syncthreads();
    if (threadIdx.x < 128) {
        atomicAdd(&g_stat[threadIdx.x], s_sum[threadIdx.x]);
        atomicAdd(&g_stat[128 + threadIdx.x], s_sq[threadIdx.x]);
    }
}

// ---------------- mma.sync GEMM, K-tiled (BK=64), ldmatrix frags, coalesced gather --
// Mainloop reordered: 3 split terms swept as separate 16-tile passes
// (accumulator RAW dependency distance 1 -> 16).
#define TILEB (128 * PADK * 2)
#define SM_AHI 0
#define SM_ALO TILEB
#define SM_BHI (2 * TILEB)
#define SM_BLO (3 * TILEB)
#define SM_AFF (4 * TILEB)                // 256 floats
#define SM_SUM (SM_AFF + 1024)
#define SM_SQ  (SM_SUM + 512)
#define SMEM_TOTAL (SM_SQ + 512)          // ~74 KB -> 2 blocks/SM (reg-limited)

__global__ void __launch_bounds__(256, 2) k_mma_gemm(
    int mode,
    const float* __restrict__ fea_i, const float* __restrict__ fea_last,
    const float* __restrict__ g1, const float* __restrict__ b1, float invc)
{
    extern __shared__ char smem[];
    int t = threadIdx.x;
    int lane = t & 31, wid = t >> 5;
    int g = lane >> 2, c4 = lane & 3;
    int wm = wid & 3, wn = wid >> 2;
    int row0 = blockIdx.x * 128;

    char* Ah = smem + SM_AHI;
    char* Al = smem + SM_ALO;
    char* Bh = smem + SM_BHI;
    char* Bl = smem + SM_BLO;
    float* s_aff = (float*)(smem + SM_AFF);
    float* s_sum = (float*)(smem + SM_SUM);
    float* s_sq  = (float*)(smem + SM_SQ);

    int wsel;
    float* C;
    const float* Asrc = nullptr;
    if (mode == 0) {
        wsel = blockIdx.y;
        Asrc = (wsel == 0) ? fea_last : fea_i;
        C = (wsel == 0) ? g_Q : (wsel == 1 ? g_K : g_V);
    } else {
        wsel = 3;
        C = g_w2;
    }

    if (mode == 1) {
        if (t < 128) {
            float mean = g_stat[t] * invc;
            float var  = g_stat[128 + t] * invc - mean * mean;
            float sc = g1[t] * rsqrtf(var + EPS);
            s_aff[t] = sc;
            s_aff[128 + t] = b1[t] - mean * sc;
            s_sum[t] = 0.f;
            s_sq[t]  = 0.f;
        }
        __syncthreads();
    }

    float acc[2][8][4];
#pragma unroll
    for (int mf = 0; mf < 2; mf++)
#pragma unroll
        for (int nf = 0; nf < 8; nf++)
#pragma unroll
            for (int e = 0; e < 4; e++) acc[mf][nf][e] = 0.f;

    int pr = t >> 1;
    int pch = (t & 1) * 32;

    const __nv_bfloat16* Wsh = g_Wbh + wsel * CIN * CIN;
    const __nv_bfloat16* Wsl = g_Wbl + wsel * CIN * CIN;

    int quad = lane >> 3, lr = lane & 7;
    int aoffe = (wm * 32 + (quad & 1) * 8 + lr) * PADK + (quad >> 1) * 8;
    int boffe = (wn * 64 + (quad >> 1) * 8 + lr) * PADK + (quad & 1) * 8;
    uint32_t uAh = smem_u32(Ah), uAl = smem_u32(Al);
    uint32_t uBh = smem_u32(Bh), uBl = smem_u32(Bl);

#pragma unroll 1
    for (int pass = 0; pass < 2; pass++) {
        int kk0 = pass * 64;
        // ---- B slice via cp.async (overlaps A prep)
        {
            const __nv_bfloat16* sh = Wsh + pr * 128 + kk0 + pch;
            const __nv_bfloat16* sl = Wsl + pr * 128 + kk0 + pch;
            uint32_t dh = smem_u32(Bh + (pr * PADK + pch) * 2);
            uint32_t dl = smem_u32(Bl + (pr * PADK + pch) * 2);
#pragma unroll
            for (int c = 0; c < 4; c++) {
                cp16(dh + c * 16, sh + c * 8);
                cp16(dl + c * 16, sl + c * 8);
            }
            CP_COMMIT();
        }
        // ---- A prep: warp-per-row coalesced; mode 1 hoists the (warp-invariant) Q row
        {
            int cg = kk0 + 2 * lane;
            float sc0 = 0.f, sc1 = 0.f, sh0 = 0.f, sh1 = 0.f;
            float2 qv = make_float2(0.f, 0.f);
            if (mode == 1) {
                sc0 = s_aff[cg];       sc1 = s_aff[cg + 1];
                sh0 = s_aff[128 + cg]; sh1 = s_aff[128 + cg + 1];
                int n = (row0 >> 4) + wid;    // all 16 rows of this warp share query n
                qv = *(const float2*)(g_Q + (size_t)n * 128 + cg);
            }
#pragma unroll
            for (int r = 0; r < 16; r++) {
                int row = wid * 16 + r;
                float x0, x1;
                if (mode == 0) {
                    float2 av = *(const float2*)(Asrc + (size_t)(row0 + row) * 128 + cg);
                    x0 = av.x; x1 = av.y;
                } else {
                    int j = g_idx[row0 + row];    // warp-uniform broadcast
                    float2 kv = *(const float2*)(g_K + (size_t)j * 128 + cg);
                    x0 = fmaf(qv.x - kv.x, sc0, sh0);
                    x1 = fmaf(qv.y - kv.y, sc1, sh1);
                    x0 = x0 >= 0.f ? x0 : SLOPE * x0;
                    x1 = x1 >= 0.f ? x1 : SLOPE * x1;
                }
                uint32_t hp, lp;
                split_pair(x0, x1, hp, lp);
                int off = (row * PADK + 2 * lane) * 2;
                *(uint32_t*)(Ah + off) = hp;
                *(uint32_t*)(Al + off) = lp;
            }
        }
        CP_WAIT0();
        __syncthreads();

        // ---- 4 K-steps of 16; term-major sweeps -> 16 independent accumulators per term
#pragma unroll
        for (int s = 0; s < 4; s++) {
            int ke = s * 16;
            uint32_t ah[8], al[8], bh[16], bl[16];
            ldsm4(&ah[0], uAh + (aoffe + ke) * 2);
            ldsm4(&ah[4], uAh + (aoffe + 16 * PADK + ke) * 2);
            ldsm4(&al[0], uAl + (aoffe + ke) * 2);
            ldsm4(&al[4], uAl + (aoffe + 16 * PADK + ke) * 2);
#pragma unroll
            for (int j = 0; j < 4; j++) {
                ldsm4(&bh[4 * j], uBh + (boffe + j * 16 * PADK + ke) * 2);
                ldsm4(&bl[4 * j], uBl + (boffe + j * 16 * PADK + ke) * 2);
            }
            // term 1: Ah * Bh (16 independent tiles)
#pragma unroll
            for (int mf = 0; mf < 2; mf++)
#pragma unroll
                for (int nf = 0; nf < 8; nf++)
                    mma16816(acc[mf][nf], &ah[4 * mf], &bh[2 * nf]);
            // term 2: Al * Bh
#pragma unroll
            for (int mf = 0; mf < 2; mf++)
#pragma unroll
                for (int nf = 0; nf < 8; nf++)
                    mma16816(acc[mf][nf], &al[4 * mf], &bh[2 * nf]);
            // term 3: Ah * Bl
#pragma unroll
            for (int mf = 0; mf < 2; mf++)
#pragma unroll
                for (int nf = 0; nf < 8; nf++)
                    mma16816(acc[mf][nf], &ah[4 * mf], &bl[2 * nf]);
        }
        __syncthreads();
    }

    // ---- epilogue
#pragma unroll
    for (int mf = 0; mf < 2; mf++)
#pragma unroll
        for (int nf = 0; nf < 8; nf++) {
            int row = row0 + wm * 32 + mf * 16 + g;
            int col = wn * 64 + nf * 8 + 2 * c4;
            *(float2*)(C + (size_t)row * 128 + col) =
                make_float2(acc[mf][nf][0], acc[mf][nf][1]);
            *(float2*)(C + (size_t)(row + 8) * 128 + col) =
                make_float2(acc[mf][nf][2], acc[mf][nf][3]);
        }

    if (mode == 1) {
#pragma unroll
        for (int nf = 0; nf < 8; nf++) {
            int col = wn * 64 + nf * 8 + 2 * c4;
            float v00 = acc[0][nf][0], v02 = acc[0][nf][2];
            float v10 = acc[1][nf][0], v12 = acc[1][nf][2];
            atomicAdd(&s_sum[col], v00 + v02 + v10 + v12);
            atomicAdd(&s_sq[col], v00 * v00 + v02 * v02 + v10 * v10 + v12 * v12);
            float v01 = acc[0][nf][1], v03 = acc[0][nf][3];
            float v11 = acc[1][nf][1], v13 = acc[1][nf][3];
            atomicAdd(&s_sum[col + 1], v01 + v03 + v11 + v13);
            atomicAdd(&s_sq[col + 1], v01 * v01 + v03 * v03 + v11 * v11 + v13 * v13);
        }
        __syncthreads();
        if (t < 128) {
            atomicAdd(&g_stat[256 + t], s_sum[t]);
            atomicAdd(&g_stat[384 + t], s_sq[t]);
        }
    }
}

// ---------------- k_out: aff2 + leaky + softmax + weighted V sum ----------------
__global__ void k_out(const float* __restrict__ bv,
                      const float* __restrict__ g2, const float* __restrict__ b2,
                      float invc, float* __restrict__ out, int N) {
    int n = blockIdx.x;
    int c = threadIdx.x;
    __shared__ int sidx[KNN];
    if (c < KNN) sidx[c] = g_idx[n * KNN + c];
    __syncthreads();

    float mean2 = g_stat[256 + c] * invc;
    float var2  = g_stat[384 + c] * invc - mean2 * mean2;
    float sc2 = g2[c] * rsqrtf(var2 + EPS);
    float sh2 = b2[c] - mean2 * sc2;

    float tv[KNN];
    float m = -1e30f;
#pragma unroll
    for (int k = 0; k < KNN; k++) {
        float x = g_w2[(size_t)(n * KNN + k) * 128 + c];
        x = fmaf(x, sc2, sh2);
        x = x >= 0.f ? x : SLOPE * x;
        tv[k] = x;
        m = fmaxf(m, x);
    }
    float s = 0.f;
#pragma unroll
    for (int k = 0; k < KNN; k++) { float e = __expf(tv[k] - m); tv[k] = e; s += e; }
    float inv = 1.f / s;
    float b = bv[c];
    float acc = 0.f;
#pragma unroll
    for (int k = 0; k < KNN; k++) {
        float v = g_V[(size_t)sidx[k] * 128 + c] + b;
        acc = fmaf(tv[k] * inv, v, acc);
    }
    out[(size_t)n * 128 + c] = acc;
}

// ---------------- launch ----------------
extern "C" void kernel_launch(void* const* d_in, const int* in_sizes, int n_in,
                              void* d_out, int out_size) {
    const float* fea_i    = (const float*)d_in[0];
    const float* fea_last = (const float*)d_in[1];
    const float* xyz_i    = (const float*)d_in[2];
    const float* xyz_last = (const float*)d_in[3];
    const float* Wq = (const float*)d_in[5];
    const float* Wk = (const float*)d_in[7];
    const float* Wv = (const float*)d_in[9];
    const float* bv = (const float*)d_in[10];
    const float* g1 = (const float*)d_in[11];
    const float* b1 = (const float*)d_in[12];
    const float* Wl = (const float*)d_in[13];
    const float* g2 = (const float*)d_in[15];
    const float* b2 = (const float*)d_in[16];

    int N = in_sizes[0] / CIN;
    float invc = 1.0f / (float)(N * KNN);

    cudaFuncSetAttribute(k_mma_gemm, cudaFuncAttributeMaxDynamicSharedMemorySize, SMEM_TOTAL);

    k_build<<<9, 1024>>>(xyz_i, Wq, Wk, Wv, Wl, N);                 // idx 0

    dim3 gq(N / 128, 3);
    k_mma_gemm<<<gq, 256, SMEM_TOTAL>>>(0, fea_i, fea_last, g1, b1, invc);  // idx 1

    k_knn_warp<<<(N + 7) / 8, 256>>>(xyz_last, N);                  // idx 2 (knn + BN1 stats)

    k_mma_gemm<<<N * KNN / 128, 256, SMEM_TOTAL>>>(1, fea_i, fea_last, g1, b1, invc); // idx 3 (profiled)

    k_out<<<N, 128>>>(bv, g2, b2, invc, (float*)d_out, N);          // idx 4
}

// round 15
// speedup vs baseline: 1.2575x; 1.1132x over previous
#include <cuda_runtime.h>
#include <cuda_fp16.h>
#include <cstdint>

#define CIN 128
#define KNN 16
#define NMAX 8192
#define EPS 1e-5f
#define SLOPE 0.01f
#define GRID 8
#define NCELL (GRID * GRID * GRID)
#define CELLH (1.0f / GRID)
#define PADK 72   // fp16 stride per smem row; ldmatrix rows differ by 4 banks -> conflict-free

// ---------------- scratch (static device memory; no allocations) ----------------
__device__ int   g_idx[NMAX * KNN];
__device__ int   g_cid[NMAX];
__device__ int   g_cellstart[NCELL + 1];
__device__ __align__(16) float4 g_cellpts[NMAX];
__device__ __align__(16) float g_Q[NMAX * CIN];
__device__ __align__(16) float g_K[NMAX * CIN];
__device__ __align__(16) float g_V[NMAX * CIN];
__device__ __align__(16) float g_w2[(size_t)NMAX * KNN * CIN];
__device__ float g_stat[4 * CIN];   // [0:128)=sum1 [128:256)=sq1 [256:384)=sum2 [384:512)=sq2
__device__ __align__(16) __half g_Wh[4 * CIN * CIN];   // Wq,Wk,Wv,Wl fp16

__device__ __forceinline__ int cell1(float x) {
    int c = (int)(x * (float)GRID);
    return c < 0 ? 0 : (c > GRID - 1 ? GRID - 1 : c);
}

__device__ __forceinline__ uint32_t smem_u32(const void* p) {
    uint32_t a;
    asm("{ .reg .u64 t; cvta.to.shared.u64 t, %1; cvt.u32.u64 %0, t; }" : "=r"(a) : "l"(p));
    return a;
}
__device__ __forceinline__ void cp16(uint32_t dst, const void* src) {
    asm volatile("cp.async.cg.shared.global [%0], [%1], 16;" :: "r"(dst), "l"(src));
}
#define CP_COMMIT() asm volatile("cp.async.commit_group;")
#define CP_WAIT0()  asm volatile("cp.async.wait_group 0;" ::: "memory")

__device__ __forceinline__ void ldsm4(uint32_t* r, uint32_t addr) {
    asm volatile("ldmatrix.sync.aligned.m8n8.x4.shared.b16 {%0,%1,%2,%3}, [%4];"
        : "=r"(r[0]), "=r"(r[1]), "=r"(r[2]), "=r"(r[3]) : "r"(addr));
}

__device__ __forceinline__ uint32_t pack_h2(float x0, float x1) {
    __half2 h = __floats2half2_rn(x0, x1);
    return *(uint32_t*)&h;
}

__device__ __forceinline__ void mma16816h(float* d, const uint32_t* a, const uint32_t* b) {
    asm volatile(
        "mma.sync.aligned.m16n8k16.row.col.f32.f16.f16.f32 "
        "{%0,%1,%2,%3}, {%4,%5,%6,%7}, {%8,%9}, {%0,%1,%2,%3};"
        : "+f"(d[0]), "+f"(d[1]), "+f"(d[2]), "+f"(d[3])
        : "r"(a[0]), "r"(a[1]), "r"(a[2]), "r"(a[3]), "r"(b[0]), "r"(b[1]));
}

// ---------------- k_build: block 0 = grid build + stat zero, blocks 1..8 = weight fp16 cvt --
__global__ void __launch_bounds__(1024) k_build(
    const float* __restrict__ xyz_i,
    const float* __restrict__ Wq, const float* __restrict__ Wk,
    const float* __restrict__ Wv, const float* __restrict__ Wl, int N)
{
    int t = threadIdx.x;
    int b = blockIdx.x;

    if (b > 0) {
        uint32_t* oh = (uint32_t*)g_Wh;
        int e0 = (b - 1) * 4096;
#pragma unroll
        for (int v = 0; v < 4; v++) {
            int e = e0 + v * 1024 + t;     // e < 32768 (4 matrices x 8192 pairs)
            int m = e >> 13;
            int off = (e & 8191) * 2;
            const float* W = (m == 0) ? Wq : (m == 1 ? Wk : (m == 2 ? Wv : Wl));
            float2 x = *(const float2*)(W + off);
            oh[e] = pack_h2(x.x, x.y);
        }
        return;
    }

    __shared__ int scnt[NCELL];
    __shared__ int spre[NCELL];
    __shared__ int scur[NCELL];

    if (t < NCELL) scnt[t] = 0;
    if (t < 4 * CIN) g_stat[t] = 0.f;
    __syncthreads();

    for (int i = t; i < N; i += 1024) {
        float x = xyz_i[i * 3 + 0], y = xyz_i[i * 3 + 1], z = xyz_i[i * 3 + 2];
        int cid = (cell1(z) * GRID + cell1(y)) * GRID + cell1(x);
        g_cid[i] = cid;
        atomicAdd(&scnt[cid], 1);
    }
    __syncthreads();

    if (t < NCELL) spre[t] = scnt[t];
    __syncthreads();
    for (int o = 1; o < NCELL; o <<= 1) {
        int v = (t >= o && t < NCELL) ? spre[t - o] : 0;
        __syncthreads();
        if (t < NCELL) spre[t] += v;
        __syncthreads();
    }
    if (t < NCELL) {
        int excl = spre[t] - scnt[t];
        g_cellstart[t] = excl;
        scur[t] = excl;
    }
    if (t == NCELL - 1) g_cellstart[NCELL] = spre[NCELL - 1];
    __syncthreads();

    for (int i = t; i < N; i += 1024) {
        float x = xyz_i[i * 3 + 0], y = xyz_i[i * 3 + 1], z = xyz_i[i * 3 + 2];
        int slot = atomicAdd(&scur[g_cid[i]], 1);
        g_cellpts[slot] = make_float4(x, y, z, __int_as_float(i));
    }
}

// ---------------- serial fallback knn (exact, shell expansion) ----------------
__device__ void knn_serial(int q, float qx, float qy, float qz, int cx, int cy, int cz) {
    float bd[KNN];
    int   bi[KNN];
#pragma unroll
    for (int s = 0; s < KNN; s++) { bd[s] = 1e30f; bi[s] = -1; }
    float curmax = 1e30f;
    int maxslot = 0;
    for (int R = 0; R < GRID; R++) {
        int zlo = cz - R < 0 ? 0 : cz - R, zhi = cz + R > GRID - 1 ? GRID - 1 : cz + R;
        int ylo = cy - R < 0 ? 0 : cy - R, yhi = cy + R > GRID - 1 ? GRID - 1 : cy + R;
        int xlo = cx - R < 0 ? 0 : cx - R, xhi = cx + R > GRID - 1 ? GRID - 1 : cx + R;
        for (int zz = zlo; zz <= zhi; zz++) {
            int adz = zz - cz; adz = adz < 0 ? -adz : adz;
            for (int yy = ylo; yy <= yhi; yy++) {
                int ady = yy - cy; ady = ady < 0 ? -ady : ady;
                int rowmax = adz > ady ? adz : ady;
                for (int xx = xlo; xx <= xhi; xx++) {
                    int adx = xx - cx; adx = adx < 0 ? -adx : adx;
                    int cheb = rowmax > adx ? rowmax : adx;
                    if (cheb != R) continue;
                    int cellid = (zz * GRID + yy) * GRID + xx;
                    int s0 = g_cellstart[cellid];
                    int s1 = g_cellstart[cellid + 1];
                    for (int s = s0; s < s1; s++) {
                        float4 p = g_cellpts[s];
                        float dx = qx - p.x, dy = qy - p.y, dz = qz - p.z;
                        float d2 = fmaf(dx, dx, fmaf(dy, dy, dz * dz));
                        if (d2 < curmax) {
                            int j = __float_as_int(p.w);
#pragma unroll
                            for (int u = 0; u < KNN; u++)
                                if (u == maxslot) { bd[u] = d2; bi[u] = j; }
                            curmax = -1.f;
#pragma unroll
                            for (int u = 0; u < KNN; u++)
                                if (bd[u] > curmax) { curmax = bd[u]; maxslot = u; }
                        }
                    }
                }
            }
        }
        float reach = (float)R * CELLH;
        if (curmax <= reach * reach) break;
    }
#pragma unroll
    for (int s = 0; s < KNN; s++) g_idx[q * KNN + s] = bi[s];
}

// ---------------- warp-per-query knn + fused BN1 stats ----------------
__global__ void __launch_bounds__(256) k_knn_warp(const float* __restrict__ xyz_last, int N) {
    __shared__ int s_pre[8][12];
    __shared__ int s_s0[8][12];
    __shared__ float s_sum[128], s_sq[128];
    int w = threadIdx.x >> 5;
    int lid = threadIdx.x & 31;
    int q = (blockIdx.x * 256 + threadIdx.x) >> 5;

    if (threadIdx.x < 128) { s_sum[threadIdx.x] = 0.f; s_sq[threadIdx.x] = 0.f; }
    __syncthreads();

    bool valid = (q < N);
    if (valid) {
        float qx = xyz_last[q * 3 + 0];
        float qy = xyz_last[q * 3 + 1];
        float qz = xyz_last[q * 3 + 2];
        int cx = cell1(qx), cy = cell1(qy), cz = cell1(qz);

        int zlo = cz - 1 < 0 ? 0 : cz - 1, zhi = cz + 1 > GRID - 1 ? GRID - 1 : cz + 1;
        int ylo = cy - 1 < 0 ? 0 : cy - 1, yhi = cy + 1 > GRID - 1 ? GRID - 1 : cy + 1;
        int xlo = cx - 1 < 0 ? 0 : cx - 1, xhi = cx + 1 > GRID - 1 ? GRID - 1 : cx + 1;
        int ny = yhi - ylo + 1;
        int nrows = (zhi - zlo + 1) * ny;   // <= 9

        int s0 = 0, len = 0;
        if (lid < nrows) {
            int zz = zlo + lid / ny;
            int yy = ylo + lid % ny;
            int cbase = (zz * GRID + yy) * GRID;
            s0 = g_cellstart[cbase + xlo];
            len = g_cellstart[cbase + xhi + 1] - s0;
        }
        int pre = len;
#pragma unroll
        for (int o = 1; o < 32; o <<= 1) {
            int v = __shfl_up_sync(0xFFFFFFFFu, pre, o);
            if (lid >= o) pre += v;
        }
        int T = __shfl_sync(0xFFFFFFFFu, pre, 31);
        int myStart = pre - len;

        if (lid < 12) { s_pre[w][lid] = 0x7FFFFFFF; s_s0[w][lid] = 0; }
        __syncwarp();
        if (lid <= nrows && lid < 10) s_pre[w][lid] = myStart;
        if (lid < nrows) s_s0[w][lid] = s0;
        __syncwarp();

        float bd[KNN];
        int   bi[KNN];
#pragma unroll
        for (int s = 0; s < KNN; s++) { bd[s] = 1e30f; bi[s] = -1; }
        float curmax = 1e30f;
        int maxslot = 0;

        int niter = (T + 31) >> 5;
        for (int it = 0; it < niter; it++) {
            int c = it * 32 + lid;
            if (c < T) {
                int j = 0;
#pragma unroll
                for (int i = 1; i <= 9; i++) j += (c >= s_pre[w][i]) ? 1 : 0;
                int slot = s_s0[w][j] + (c - s_pre[w][j]);
                float4 p = g_cellpts[slot];
                float dx = qx - p.x, dy = qy - p.y, dz = qz - p.z;
                float d2 = fmaf(dx, dx, fmaf(dy, dy, dz * dz));
                if (d2 < curmax) {
                    int ji = __float_as_int(p.w);
#pragma unroll
                    for (int u = 0; u < KNN; u++)
                        if (u == maxslot) { bd[u] = d2; bi[u] = ji; }
                    curmax = -1.f;
#pragma unroll
                    for (int u = 0; u < KNN; u++)
                        if (bd[u] > curmax) { curmax = bd[u]; maxslot = u; }
                }
            }
        }

        float lmin = 1e30f;
        int lslot = 0;
#pragma unroll
        for (int s = 0; s < KNN; s++)
            if (bd[s] < lmin) { lmin = bd[s]; lslot = s; }

        float d16 = 0.f;
        int myres = -1;
        for (int r = 0; r < KNN; r++) {
            float v = lmin;
            int wl = lid;
#pragma unroll
            for (int o = 16; o; o >>= 1) {
                float ov = __shfl_xor_sync(0xFFFFFFFFu, v, o);
                int owl = __shfl_xor_sync(0xFFFFFFFFu, wl, o);
                if (ov < v || (ov == v && owl < wl)) { v = ov; wl = owl; }
            }
            int myidx = -1;
#pragma unroll
            for (int s = 0; s < KNN; s++)
                if (s == lslot) myidx = bi[s];
            int wi = __shfl_sync(0xFFFFFFFFu, myidx, wl);
            d16 = v;
            if (lid == r) myres = wi;
            if (lid == wl) {
#pragma unroll
                for (int s = 0; s < KNN; s++)
                    if (s == lslot) bd[s] = 1e30f;
                lmin = 1e30f; lslot = 0;
#pragma unroll
                for (int s = 0; s < KNN; s++)
                    if (bd[s] < lmin) { lmin = bd[s]; lslot = s; }
            }
        }

        if (d16 <= CELLH * CELLH) {
            if (lid < KNN) g_idx[q * KNN + lid] = myres;
        } else {
            if (lid == 0) knn_serial(q, qx, qy, qz, cx, cy, cz);
        }
        __syncwarp();

        // fused BN1 stats: lane owns 4 channels of query q
        {
            int cb = lid * 4;
            float4 Qv = *(const float4*)(g_Q + (size_t)q * 128 + cb);
            float S0 = 0.f, S1 = 0.f, S2 = 0.f, S3 = 0.f;
            float T0 = 0.f, T1 = 0.f, T2 = 0.f, T3 = 0.f;
#pragma unroll
            for (int k = 0; k < KNN; k++) {
                int j = g_idx[q * KNN + k];
                float4 kv = *(const float4*)(g_K + (size_t)j * 128 + cb);
                S0 += kv.x; T0 = fmaf(kv.x, kv.x, T0);
                S1 += kv.y; T1 = fmaf(kv.y, kv.y, T1);
                S2 += kv.z; T2 = fmaf(kv.z, kv.z, T2);
                S3 += kv.w; T3 = fmaf(kv.w, kv.w, T3);
            }
            atomicAdd(&s_sum[cb + 0], 16.f * Qv.x - S0);
            atomicAdd(&s_sum[cb + 1], 16.f * Qv.y - S1);
            atomicAdd(&s_sum[cb + 2], 16.f * Qv.z - S2);
            atomicAdd(&s_sum[cb + 3], 16.f * Qv.w - S3);
            atomicAdd(&s_sq[cb + 0], fmaf(16.f * Qv.x, Qv.x, fmaf(-2.f * Qv.x, S0, T0)));
            atomicAdd(&s_sq[cb + 1], fmaf(16.f * Qv.y, Qv.y, fmaf(-2.f * Qv.y, S1, T1)));
            atomicAdd(&s_sq[cb + 2], fmaf(16.f * Qv.z, Qv.z, fmaf(-2.f * Qv.z, S2, T2)));
            atomicAdd(&s_sq[cb + 3], fmaf(16.f * Qv.w, Qv.w, fmaf(-2.f * Qv.w, S3, T3)));
        }
    }
    __syncthreads();
    if (threadIdx.x < 128) {
        atomicAdd(&g_stat[threadIdx.x], s_sum[threadIdx.x]);
        atomicAdd(&g_stat[128 + threadIdx.x], s_sq[threadIdx.x]);
    }
}

// ---------------- mma.sync GEMM, fp16 single-term, K-tiled (BK=64) ----------------
#define TILEB (128 * PADK * 2)            // 18432 bytes (fp16 tile)
#define SM_AH 0
#define SM_BH TILEB
#define SM_AFF (2 * TILEB)                // 256 floats
#define SM_SUM (SM_AFF + 1024)
#define SM_SQ  (SM_SUM + 512)
#define SMEM_TOTAL (SM_SQ + 512)          // ~38.4 KB

__global__ void __launch_bounds__(256, 2) k_mma_gemm(
    int mode,
    const float* __restrict__ fea_i, const float* __restrict__ fea_last,
    const float* __restrict__ g1, const float* __restrict__ b1, float invc)
{
    extern __shared__ char smem[];
    int t = threadIdx.x;
    int lane = t & 31, wid = t >> 5;
    int g = lane >> 2, c4 = lane & 3;
    int wm = wid & 3, wn = wid >> 2;
    int row0 = blockIdx.x * 128;

    char* Ah = smem + SM_AH;
    char* Bh = smem + SM_BH;
    float* s_aff = (float*)(smem + SM_AFF);
    float* s_sum = (float*)(smem + SM_SUM);
    float* s_sq  = (float*)(smem + SM_SQ);

    int wsel;
    float* C;
    const float* Asrc = nullptr;
    if (mode == 0) {
        wsel = blockIdx.y;
        Asrc = (wsel == 0) ? fea_last : fea_i;
        C = (wsel == 0) ? g_Q : (wsel == 1 ? g_K : g_V);
    } else {
        wsel = 3;
        C = g_w2;
    }

    if (mode == 1) {
        if (t < 128) {
            float mean = g_stat[t] * invc;
            float var  = g_stat[128 + t] * invc - mean * mean;
            float sc = g1[t] * rsqrtf(var + EPS);
            s_aff[t] = sc;
            s_aff[128 + t] = b1[t] - mean * sc;
            s_sum[t] = 0.f;
            s_sq[t]  = 0.f;
        }
        __syncthreads();
    }

    float acc[2][8][4];
#pragma unroll
    for (int mf = 0; mf < 2; mf++)
#pragma unroll
        for (int nf = 0; nf < 8; nf++)
#pragma unroll
            for (int e = 0; e < 4; e++) acc[mf][nf][e] = 0.f;

    int pr = t >> 1;
    int pch = (t & 1) * 32;

    const __half* Wsh = g_Wh + wsel * CIN * CIN;

    int quad = lane >> 3, lr = lane & 7;
    int aoffe = (wm * 32 + (quad & 1) * 8 + lr) * PADK + (quad >> 1) * 8;
    int boffe = (wn * 64 + (quad >> 1) * 8 + lr) * PADK + (quad & 1) * 8;
    uint32_t uAh = smem_u32(Ah);
    uint32_t uBh = smem_u32(Bh);

#pragma unroll 1
    for (int pass = 0; pass < 2; pass++) {
        int kk0 = pass * 64;
        // ---- B slice via cp.async (overlaps A prep)
        {
            const __half* sh = Wsh + pr * 128 + kk0 + pch;
            uint32_t dh = smem_u32(Bh + (pr * PADK + pch) * 2);
#pragma unroll
            for (int c = 0; c < 4; c++)
                cp16(dh + c * 16, sh + c * 8);
            CP_COMMIT();
        }
        // ---- A prep: warp-per-row coalesced; mode 1 hoists the (warp-invariant) Q row
        {
            int cg = kk0 + 2 * lane;
            float sc0 = 0.f, sc1 = 0.f, sh0 = 0.f, sh1 = 0.f;
            float2 qv = make_float2(0.f, 0.f);
            if (mode == 1) {
                sc0 = s_aff[cg];       sc1 = s_aff[cg + 1];
                sh0 = s_aff[128 + cg]; sh1 = s_aff[128 + cg + 1];
                int n = (row0 >> 4) + wid;    // all 16 rows of this warp share query n
                qv = *(const float2*)(g_Q + (size_t)n * 128 + cg);
            }
#pragma unroll
            for (int r = 0; r < 16; r++) {
                int row = wid * 16 + r;
                float x0, x1;
                if (mode == 0) {
                    float2 av = *(const float2*)(Asrc + (size_t)(row0 + row) * 128 + cg);
                    x0 = av.x; x1 = av.y;
                } else {
                    int j = g_idx[row0 + row];    // warp-uniform broadcast
                    float2 kv = *(const float2*)(g_K + (size_t)j * 128 + cg);
                    x0 = fmaf(qv.x - kv.x, sc0, sh0);
                    x1 = fmaf(qv.y - kv.y, sc1, sh1);
                    x0 = x0 >= 0.f ? x0 : SLOPE * x0;
                    x1 = x1 >= 0.f ? x1 : SLOPE * x1;
                }
                *(uint32_t*)(Ah + (row * PADK + 2 * lane) * 2) = pack_h2(x0, x1);
            }
        }
        CP_WAIT0();
        __syncthreads();

        // ---- 4 K-steps of 16, single fp16 term (16 mma per k-step)
#pragma unroll
        for (int s = 0; s < 4; s++) {
            int ke = s * 16;
            uint32_t ah[8], bh[16];
            ldsm4(&ah[0], uAh + (aoffe + ke) * 2);
            ldsm4(&ah[4], uAh + (aoffe + 16 * PADK + ke) * 2);
#pragma unroll
            for (int j = 0; j < 4; j++)
                ldsm4(&bh[4 * j], uBh + (boffe + j * 16 * PADK + ke) * 2);
#pragma unroll
            for (int mf = 0; mf < 2; mf++)
#pragma unroll
                for (int nf = 0; nf < 8; nf++)
                    mma16816h(acc[mf][nf], &ah[4 * mf], &bh[2 * nf]);
        }
        __syncthreads();
    }

    // ---- epilogue
#pragma unroll
    for (int mf = 0; mf < 2; mf++)
#pragma unroll
        for (int nf = 0; nf < 8; nf++) {
            int row = row0 + wm * 32 + mf * 16 + g;
            int col = wn * 64 + nf * 8 + 2 * c4;
            *(float2*)(C + (size_t)row * 128 + col) =
                make_float2(acc[mf][nf][0], acc[mf][nf][1]);
            *(float2*)(C + (size_t)(row + 8) * 128 + col) =
                make_float2(acc[mf][nf][2], acc[mf][nf][3]);
        }

    if (mode == 1) {
#pragma unroll
        for (int nf = 0; nf < 8; nf++) {
            int col = wn * 64 + nf * 8 + 2 * c4;
            float v00 = acc[0][nf][0], v02 = acc[0][nf][2];
            float v10 = acc[1][nf][0], v12 = acc[1][nf][2];
            atomicAdd(&s_sum[col], v00 + v02 + v10 + v12);
            atomicAdd(&s_sq[col], v00 * v00 + v02 * v02 + v10 * v10 + v12 * v12);
            float v01 = acc[0][nf][1], v03 = acc[0][nf][3];
            float v11 = acc[1][nf][1], v13 = acc[1][nf][3];
            atomicAdd(&s_sum[col + 1], v01 + v03 + v11 + v13);
            atomicAdd(&s_sq[col + 1], v01 * v01 + v03 * v03 + v11 * v11 + v13 * v13);
        }
        __syncthreads();
        if (t < 128) {
            atomicAdd(&g_stat[256 + t], s_sum[t]);
            atomicAdd(&g_stat[384 + t], s_sq[t]);
        }
    }
}

// ---------------- k_out: aff2 + leaky + softmax + weighted V sum ----------------
__global__ void k_out(const float* __restrict__ bv,
                      const float* __restrict__ g2, const float* __restrict__ b2,
                      float invc, float* __restrict__ out, int N) {
    int n = blockIdx.x;
    int c = threadIdx.x;
    __shared__ int sidx[KNN];
    if (c < KNN) sidx[c] = g_idx[n * KNN + c];
    __syncthreads();

    float mean2 = g_stat[256 + c] * invc;
    float var2  = g_stat[384 + c] * invc - mean2 * mean2;
    float sc2 = g2[c] * rsqrtf(var2 + EPS);
    float sh2 = b2[c] - mean2 * sc2;

    float tv[KNN];
    float m = -1e30f;
#pragma unroll
    for (int k = 0; k < KNN; k++) {
        float x = g_w2[(size_t)(n * KNN + k) * 128 + c];
        x = fmaf(x, sc2, sh2);
        x = x >= 0.f ? x : SLOPE * x;
        tv[k] = x;
        m = fmaxf(m, x);
    }
    float s = 0.f;
#pragma unroll
    for (int k = 0; k < KNN; k++) { float e = __expf(tv[k] - m); tv[k] = e; s += e; }
    float inv = 1.f / s;
    float b = bv[c];
    float acc = 0.f;
#pragma unroll
    for (int k = 0; k < KNN; k++) {
        float v = g_V[(size_t)sidx[k] * 128 + c] + b;
        acc = fmaf(tv[k] * inv, v, acc);
    }
    out[(size_t)n * 128 + c] = acc;
}

// ---------------- launch ----------------
extern "C" void kernel_launch(void* const* d_in, const int* in_sizes, int n_in,
                              void* d_out, int out_size) {
    const float* fea_i    = (const float*)d_in[0];
    const float* fea_last = (const float*)d_in[1];
    const float* xyz_i    = (const float*)d_in[2];
    const float* xyz_last = (const float*)d_in[3];
    const float* Wq = (const float*)d_in[5];
    const float* Wk = (const float*)d_in[7];
    const float* Wv = (const float*)d_in[9];
    const float* bv = (const float*)d_in[10];
    const float* g1 = (const float*)d_in[11];
    const float* b1 = (const float*)d_in[12];
    const float* Wl = (const float*)d_in[13];
    const float* g2 = (const float*)d_in[15];
    const float* b2 = (const float*)d_in[16];

    int N = in_sizes[0] / CIN;
    float invc = 1.0f / (float)(N * KNN);

    cudaFuncSetAttribute(k_mma_gemm, cudaFuncAttributeMaxDynamicSharedMemorySize, SMEM_TOTAL);

    k_build<<<9, 1024>>>(xyz_i, Wq, Wk, Wv, Wl, N);                 // idx 0

    dim3 gq(N / 128, 3);
    k_mma_gemm<<<gq, 256, SMEM_TOTAL>>>(0, fea_i, fea_last, g1, b1, invc);  // idx 1

    k_knn_warp<<<(N + 7) / 8, 256>>>(xyz_last, N);                  // idx 2 (knn + BN1 stats)

    k_mma_gemm<<<N * KNN / 128, 256, SMEM_TOTAL>>>(1, fea_i, fea_last, g1, b1, invc); // idx 3 (profiled)

    k_out<<<N, 128>>>(bv, g2, b2, invc, (float*)d_out, N);          // idx 4
}

// round 16
// speedup vs baseline: 1.2625x; 1.0040x over previous
#include <cuda_runtime.h>
#include <cuda_fp16.h>
#include <cstdint>

#define CIN 128
#define KNN 16
#define NMAX 8192
#define EPS 1e-5f
#define SLOPE 0.01f
#define GRID 8
#define NCELL (GRID * GRID * GRID)
#define CELLH (1.0f / GRID)
#define PADK 136  // fp16 stride per smem row (full K); ldmatrix rows differ by 4 banks

// ---------------- scratch (static device memory; no allocations) ----------------
__device__ int   g_idx[NMAX * KNN];
__device__ int   g_cid[NMAX];
__device__ int   g_cellstart[NCELL + 1];
__device__ __align__(16) float4 g_cellpts[NMAX];
__device__ __align__(16) float g_Q[NMAX * CIN];
__device__ __align__(16) float g_K[NMAX * CIN];
__device__ __align__(16) float g_V[NMAX * CIN];
__device__ __align__(16) float g_w2[(size_t)NMAX * KNN * CIN];
__device__ float g_stat[4 * CIN];   // [0:128)=sum1 [128:256)=sq1 [256:384)=sum2 [384:512)=sq2
__device__ __align__(16) __half g_Wh[4 * CIN * CIN];   // Wq,Wk,Wv,Wl fp16

__device__ __forceinline__ int cell1(float x) {
    int c = (int)(x * (float)GRID);
    return c < 0 ? 0 : (c > GRID - 1 ? GRID - 1 : c);
}

__device__ __forceinline__ uint32_t smem_u32(const void* p) {
    uint32_t a;
    asm("{ .reg .u64 t; cvta.to.shared.u64 t, %1; cvt.u32.u64 %0, t; }" : "=r"(a) : "l"(p));
    return a;
}
__device__ __forceinline__ void cp16(uint32_t dst, const void* src) {
    asm volatile("cp.async.cg.shared.global [%0], [%1], 16;" :: "r"(dst), "l"(src));
}
#define CP_COMMIT() asm volatile("cp.async.commit_group;")
#define CP_WAIT0()  asm volatile("cp.async.wait_group 0;" ::: "memory")

__device__ __forceinline__ void ldsm4(uint32_t* r, uint32_t addr) {
    asm volatile("ldmatrix.sync.aligned.m8n8.x4.shared.b16 {%0,%1,%2,%3}, [%4];"
        : "=r"(r[0]), "=r"(r[1]), "=r"(r[2]), "=r"(r[3]) : "r"(addr));
}

__device__ __forceinline__ uint32_t pack_h2(float x0, float x1) {
    __half2 h = __floats2half2_rn(x0, x1);
    return *(uint32_t*)&h;
}

__device__ __forceinline__ void mma16816h(float* d, const uint32_t* a, const uint32_t* b) {
    asm volatile(
        "mma.sync.aligned.m16n8k16.row.col.f32.f16.f16.f32 "
        "{%0,%1,%2,%3}, {%4,%5,%6,%7}, {%8,%9}, {%0,%1,%2,%3};"
        : "+f"(d[0]), "+f"(d[1]), "+f"(d[2]), "+f"(d[3])
        : "r"(a[0]), "r"(a[1]), "r"(a[2]), "r"(a[3]), "r"(b[0]), "r"(b[1]));
}

// ---------------- k_build: block 0 = grid build + stat zero, blocks 1..8 = weight fp16 cvt --
__global__ void __launch_bounds__(1024) k_build(
    const float* __restrict__ xyz_i,
    const float* __restrict__ Wq, const float* __restrict__ Wk,
    const float* __restrict__ Wv, const float* __restrict__ Wl, int N)
{
    int t = threadIdx.x;
    int b = blockIdx.x;

    if (b > 0) {
        uint32_t* oh = (uint32_t*)g_Wh;
        int e0 = (b - 1) * 4096;
#pragma unroll
        for (int v = 0; v < 4; v++) {
            int e = e0 + v * 1024 + t;
            int m = e >> 13;
            int off = (e & 8191) * 2;
            const float* W = (m == 0) ? Wq : (m == 1 ? Wk : (m == 2 ? Wv : Wl));
            float2 x = *(const float2*)(W + off);
            oh[e] = pack_h2(x.x, x.y);
        }
        return;
    }

    __shared__ int scnt[NCELL];
    __shared__ int spre[NCELL];
    __shared__ int scur[NCELL];

    if (t < NCELL) scnt[t] = 0;
    if (t < 4 * CIN) g_stat[t] = 0.f;
    __syncthreads();

    for (int i = t; i < N; i += 1024) {
        float x = xyz_i[i * 3 + 0], y = xyz_i[i * 3 + 1], z = xyz_i[i * 3 + 2];
        int cid = (cell1(z) * GRID + cell1(y)) * GRID + cell1(x);
        g_cid[i] = cid;
        atomicAdd(&scnt[cid], 1);
    }
    __syncthreads();

    if (t < NCELL) spre[t] = scnt[t];
    __syncthreads();
    for (int o = 1; o < NCELL; o <<= 1) {
        int v = (t >= o && t < NCELL) ? spre[t - o] : 0;
        __syncthreads();
        if (t < NCELL) spre[t] += v;
        __syncthreads();
    }
    if (t < NCELL) {
        int excl = spre[t] - scnt[t];
        g_cellstart[t] = excl;
        scur[t] = excl;
    }
    if (t == NCELL - 1) g_cellstart[NCELL] = spre[NCELL - 1];
    __syncthreads();

    for (int i = t; i < N; i += 1024) {
        float x = xyz_i[i * 3 + 0], y = xyz_i[i * 3 + 1], z = xyz_i[i * 3 + 2];
        int slot = atomicAdd(&scur[g_cid[i]], 1);
        g_cellpts[slot] = make_float4(x, y, z, __int_as_float(i));
    }
}

// ---------------- serial fallback knn (exact, shell expansion) ----------------
__device__ void knn_serial(int q, float qx, float qy, float qz, int cx, int cy, int cz) {
    float bd[KNN];
    int   bi[KNN];
#pragma unroll
    for (int s = 0; s < KNN; s++) { bd[s] = 1e30f; bi[s] = -1; }
    float curmax = 1e30f;
    int maxslot = 0;
    for (int R = 0; R < GRID; R++) {
        int zlo = cz - R < 0 ? 0 : cz - R, zhi = cz + R > GRID - 1 ? GRID - 1 : cz + R;
        int ylo = cy - R < 0 ? 0 : cy - R, yhi = cy + R > GRID - 1 ? GRID - 1 : cy + R;
        int xlo = cx - R < 0 ? 0 : cx - R, xhi = cx + R > GRID - 1 ? GRID - 1 : cx + R;
        for (int zz = zlo; zz <= zhi; zz++) {
            int adz = zz - cz; adz = adz < 0 ? -adz : adz;
            for (int yy = ylo; yy <= yhi; yy++) {
                int ady = yy - cy; ady = ady < 0 ? -ady : ady;
                int rowmax = adz > ady ? adz : ady;
                for (int xx = xlo; xx <= xhi; xx++) {
                    int adx = xx - cx; adx = adx < 0 ? -adx : adx;
                    int cheb = rowmax > adx ? rowmax : adx;
                    if (cheb != R) continue;
                    int cellid = (zz * GRID + yy) * GRID + xx;
                    int s0 = g_cellstart[cellid];
                    int s1 = g_cellstart[cellid + 1];
                    for (int s = s0; s < s1; s++) {
                        float4 p = g_cellpts[s];
                        float dx = qx - p.x, dy = qy - p.y, dz = qz - p.z;
                        float d2 = fmaf(dx, dx, fmaf(dy, dy, dz * dz));
                        if (d2 < curmax) {
                            int j = __float_as_int(p.w);
#pragma unroll
                            for (int u = 0; u < KNN; u++)
                                if (u == maxslot) { bd[u] = d2; bi[u] = j; }
                            curmax = -1.f;
#pragma unroll
                            for (int u = 0; u < KNN; u++)
                                if (bd[u] > curmax) { curmax = bd[u]; maxslot = u; }
                        }
                    }
                }
            }
        }
        float reach = (float)R * CELLH;
        if (curmax <= reach * reach) break;
    }
#pragma unroll
    for (int s = 0; s < KNN; s++) g_idx[q * KNN + s] = bi[s];
}

// ---------------- warp-per-query knn + fused BN1 stats ----------------
__global__ void __launch_bounds__(256) k_knn_warp(const float* __restrict__ xyz_last, int N) {
    __shared__ int s_pre[8][12];
    __shared__ int s_s0[8][12];
    __shared__ float s_sum[128], s_sq[128];
    int w = threadIdx.x >> 5;
    int lid = threadIdx.x & 31;
    int q = (blockIdx.x * 256 + threadIdx.x) >> 5;

    if (threadIdx.x < 128) { s_sum[threadIdx.x] = 0.f; s_sq[threadIdx.x] = 0.f; }
    __syncthreads();

    bool valid = (q < N);
    if (valid) {
        float qx = xyz_last[q * 3 + 0];
        float qy = xyz_last[q * 3 + 1];
        float qz = xyz_last[q * 3 + 2];
        int cx = cell1(qx), cy = cell1(qy), cz = cell1(qz);

        int zlo = cz - 1 < 0 ? 0 : cz - 1, zhi = cz + 1 > GRID - 1 ? GRID - 1 : cz + 1;
        int ylo = cy - 1 < 0 ? 0 : cy - 1, yhi = cy + 1 > GRID - 1 ? GRID - 1 : cy + 1;
        int xlo = cx - 1 < 0 ? 0 : cx - 1, xhi = cx + 1 > GRID - 1 ? GRID - 1 : cx + 1;
        int ny = yhi - ylo + 1;
        int nrows = (zhi - zlo + 1) * ny;   // <= 9

        int s0 = 0, len = 0;
        if (lid < nrows) {
            int zz = zlo + lid / ny;
            int yy = ylo + lid % ny;
            int cbase = (zz * GRID + yy) * GRID;
            s0 = g_cellstart[cbase + xlo];
            len = g_cellstart[cbase + xhi + 1] - s0;
        }
        int pre = len;
#pragma unroll
        for (int o = 1; o < 32; o <<= 1) {
            int v = __shfl_up_sync(0xFFFFFFFFu, pre, o);
            if (lid >= o) pre += v;
        }
        int T = __shfl_sync(0xFFFFFFFFu, pre, 31);
        int myStart = pre - len;

        if (lid < 12) { s_pre[w][lid] = 0x7FFFFFFF; s_s0[w][lid] = 0; }
        __syncwarp();
        if (lid <= nrows && lid < 10) s_pre[w][lid] = myStart;
        if (lid < nrows) s_s0[w][lid] = s0;
        __syncwarp();

        float bd[KNN];
        int   bi[KNN];
#pragma unroll
        for (int s = 0; s < KNN; s++) { bd[s] = 1e30f; bi[s] = -1; }
        float curmax = 1e30f;
        int maxslot = 0;

        int niter = (T + 31) >> 5;
        for (int it = 0; it < niter; it++) {
            int c = it * 32 + lid;
            if (c < T) {
                int j = 0;
#pragma unroll
                for (int i = 1; i <= 9; i++) j += (c >= s_pre[w][i]) ? 1 : 0;
                int slot = s_s0[w][j] + (c - s_pre[w][j]);
                float4 p = g_cellpts[slot];
                float dx = qx - p.x, dy = qy - p.y, dz = qz - p.z;
                float d2 = fmaf(dx, dx, fmaf(dy, dy, dz * dz));
                if (d2 < curmax) {
                    int ji = __float_as_int(p.w);
#pragma unroll
                    for (int u = 0; u < KNN; u++)
                        if (u == maxslot) { bd[u] = d2; bi[u] = ji; }
                    curmax = -1.f;
#pragma unroll
                    for (int u = 0; u < KNN; u++)
                        if (bd[u] > curmax) { curmax = bd[u]; maxslot = u; }
                }
            }
        }

        float lmin = 1e30f;
        int lslot = 0;
#pragma unroll
        for (int s = 0; s < KNN; s++)
            if (bd[s] < lmin) { lmin = bd[s]; lslot = s; }

        float d16 = 0.f;
        int myres = -1;
        for (int r = 0; r < KNN; r++) {
            float v = lmin;
            int wl = lid;
#pragma unroll
            for (int o = 16; o; o >>= 1) {
                float ov = __shfl_xor_sync(0xFFFFFFFFu, v, o);
                int owl = __shfl_xor_sync(0xFFFFFFFFu, wl, o);
                if (ov < v || (ov == v && owl < wl)) { v = ov; wl = owl; }
            }
            int myidx = -1;
#pragma unroll
            for (int s = 0; s < KNN; s++)
                if (s == lslot) myidx = bi[s];
            int wi = __shfl_sync(0xFFFFFFFFu, myidx, wl);
            d16 = v;
            if (lid == r) myres = wi;
            if (lid == wl) {
#pragma unroll
                for (int s = 0; s < KNN; s++)
                    if (s == lslot) bd[s] = 1e30f;
                lmin = 1e30f; lslot = 0;
#pragma unroll
                for (int s = 0; s < KNN; s++)
                    if (bd[s] < lmin) { lmin = bd[s]; lslot = s; }
            }
        }

        if (d16 <= CELLH * CELLH) {
            if (lid < KNN) g_idx[q * KNN + lid] = myres;
        } else {
            if (lid == 0) knn_serial(q, qx, qy, qz, cx, cy, cz);
        }
        __syncwarp();

        // fused BN1 stats: lane owns 4 channels of query q
        {
            int cb = lid * 4;
            float4 Qv = *(const float4*)(g_Q + (size_t)q * 128 + cb);
            float S0 = 0.f, S1 = 0.f, S2 = 0.f, S3 = 0.f;
            float T0 = 0.f, T1 = 0.f, T2 = 0.f, T3 = 0.f;
#pragma unroll
            for (int k = 0; k < KNN; k++) {
                int j = g_idx[q * KNN + k];
                float4 kv = *(const float4*)(g_K + (size_t)j * 128 + cb);
                S0 += kv.x; T0 = fmaf(kv.x, kv.x, T0);
                S1 += kv.y; T1 = fmaf(kv.y, kv.y, T1);
                S2 += kv.z; T2 = fmaf(kv.z, kv.z, T2);
                S3 += kv.w; T3 = fmaf(kv.w, kv.w, T3);
            }
            atomicAdd(&s_sum[cb + 0], 16.f * Qv.x - S0);
            atomicAdd(&s_sum[cb + 1], 16.f * Qv.y - S1);
            atomicAdd(&s_sum[cb + 2], 16.f * Qv.z - S2);
            atomicAdd(&s_sum[cb + 3], 16.f * Qv.w - S3);
            atomicAdd(&s_sq[cb + 0], fmaf(16.f * Qv.x, Qv.x, fmaf(-2.f * Qv.x, S0, T0)));
            atomicAdd(&s_sq[cb + 1], fmaf(16.f * Qv.y, Qv.y, fmaf(-2.f * Qv.y, S1, T1)));
            atomicAdd(&s_sq[cb + 2], fmaf(16.f * Qv.z, Qv.z, fmaf(-2.f * Qv.z, S2, T2)));
            atomicAdd(&s_sq[cb + 3], fmaf(16.f * Qv.w, Qv.w, fmaf(-2.f * Qv.w, S3, T3)));
        }
    }
    __syncthreads();
    if (threadIdx.x < 128) {
        atomicAdd(&g_stat[threadIdx.x], s_sum[threadIdx.x]);
        atomicAdd(&g_stat[128 + threadIdx.x], s_sq[threadIdx.x]);
    }
}

// ---------------- mma.sync GEMM, fp16 single-term, single full-K pass ----------------
#define TILEB (128 * PADK * 2)            // 34816 bytes
#define SM_AH 0
#define SM_BH TILEB
#define SM_AFF (2 * TILEB)                // 256 floats
#define SM_SUM (SM_AFF + 1024)
#define SM_SQ  (SM_SUM + 512)
#define SMEM_TOTAL (SM_SQ + 512)          // ~71.7 KB -> 2 blocks/SM

__global__ void __launch_bounds__(256, 2) k_mma_gemm(
    int mode,
    const float* __restrict__ fea_i, const float* __restrict__ fea_last,
    const float* __restrict__ g1, const float* __restrict__ b1, float invc)
{
    extern __shared__ char smem[];
    int t = threadIdx.x;
    int lane = t & 31, wid = t >> 5;
    int g = lane >> 2, c4 = lane & 3;
    int wm = wid & 3, wn = wid >> 2;
    int row0 = blockIdx.x * 128;

    char* Ah = smem + SM_AH;
    char* Bh = smem + SM_BH;
    float* s_aff = (float*)(smem + SM_AFF);
    float* s_sum = (float*)(smem + SM_SUM);
    float* s_sq  = (float*)(smem + SM_SQ);

    int wsel;
    float* C;
    const float* Asrc = nullptr;
    if (mode == 0) {
        wsel = blockIdx.y;
        Asrc = (wsel == 0) ? fea_last : fea_i;
        C = (wsel == 0) ? g_Q : (wsel == 1 ? g_K : g_V);
    } else {
        wsel = 3;
        C = g_w2;
    }

    // ---- B tile via cp.async: thread covers 64 cols of row pr (128B = 8 cp16)
    {
        int pr = t >> 1;
        int pch = (t & 1) * 64;
        const __half* sh = g_Wh + wsel * CIN * CIN + pr * 128 + pch;
        uint32_t dh = smem_u32(Bh + (pr * PADK + pch) * 2);
#pragma unroll
        for (int c = 0; c < 8; c++)
            cp16(dh + c * 16, sh + c * 8);
        CP_COMMIT();
    }

    if (mode == 1) {
        if (t < 128) {
            float mean = g_stat[t] * invc;
            float var  = g_stat[128 + t] * invc - mean * mean;
            float sc = g1[t] * rsqrtf(var + EPS);
            s_aff[t] = sc;
            s_aff[128 + t] = b1[t] - mean * sc;
            s_sum[t] = 0.f;
            s_sq[t]  = 0.f;
        }
        __syncthreads();   // s_aff visible before A prep reads it
    }

    float acc[2][8][4];
#pragma unroll
    for (int mf = 0; mf < 2; mf++)
#pragma unroll
        for (int nf = 0; nf < 8; nf++)
#pragma unroll
            for (int e = 0; e < 4; e++) acc[mf][nf][e] = 0.f;

    // ---- A prep: warp-per-row, lane covers cols 4*lane..4*lane+3 (float4, full K)
    {
        int cg = 4 * lane;
        float4 sc4 = make_float4(0.f, 0.f, 0.f, 0.f);
        float4 sh4 = make_float4(0.f, 0.f, 0.f, 0.f);
        float4 qv = make_float4(0.f, 0.f, 0.f, 0.f);
        if (mode == 1) {
            sc4 = *(const float4*)&s_aff[cg];
            sh4 = *(const float4*)&s_aff[128 + cg];
            int n = (row0 >> 4) + wid;    // all 16 rows of this warp share query n
            qv = *(const float4*)(g_Q + (size_t)n * 128 + cg);
        }
#pragma unroll
        for (int r = 0; r < 16; r++) {
            int row = wid * 16 + r;
            float x0, x1, x2, x3;
            if (mode == 0) {
                float4 av = *(const float4*)(Asrc + (size_t)(row0 + row) * 128 + cg);
                x0 = av.x; x1 = av.y; x2 = av.z; x3 = av.w;
            } else {
                int j = g_idx[row0 + row];    // warp-uniform broadcast
                float4 kv = *(const float4*)(g_K + (size_t)j * 128 + cg);
                x0 = fmaf(qv.x - kv.x, sc4.x, sh4.x);
                x1 = fmaf(qv.y - kv.y, sc4.y, sh4.y);
                x2 = fmaf(qv.z - kv.z, sc4.z, sh4.z);
                x3 = fmaf(qv.w - kv.w, sc4.w, sh4.w);
                x0 = x0 >= 0.f ? x0 : SLOPE * x0;
                x1 = x1 >= 0.f ? x1 : SLOPE * x1;
                x2 = x2 >= 0.f ? x2 : SLOPE * x2;
                x3 = x3 >= 0.f ? x3 : SLOPE * x3;
            }
            uint32_t* dst = (uint32_t*)(Ah + (row * PADK + cg) * 2);
            dst[0] = pack_h2(x0, x1);
            dst[1] = pack_h2(x2, x3);
        }
    }
    CP_WAIT0();
    __syncthreads();

    // ---- per-lane ldmatrix base offsets (fp16-element units)
    int quad = lane >> 3, lr = lane & 7;
    int aoffe = (wm * 32 + (quad & 1) * 8 + lr) * PADK + (quad >> 1) * 8;
    int boffe = (wn * 64 + (quad >> 1) * 8 + lr) * PADK + (quad & 1) * 8;
    uint32_t uAh = smem_u32(Ah);
    uint32_t uBh = smem_u32(Bh);

    // ---- 8 K-steps of 16, single fp16 term
#pragma unroll
    for (int s = 0; s < 8; s++) {
        int ke = s * 16;
        uint32_t ah[8], bh[16];
        ldsm4(&ah[0], uAh + (aoffe + ke) * 2);
        ldsm4(&ah[4], uAh + (aoffe + 16 * PADK + ke) * 2);
#pragma unroll
        for (int j = 0; j < 4; j++)
            ldsm4(&bh[4 * j], uBh + (boffe + j * 16 * PADK + ke) * 2);
#pragma unroll
        for (int mf = 0; mf < 2; mf++)
#pragma unroll
            for (int nf = 0; nf < 8; nf++)
                mma16816h(acc[mf][nf], &ah[4 * mf], &bh[2 * nf]);
    }

    // ---- epilogue
#pragma unroll
    for (int mf = 0; mf < 2; mf++)
#pragma unroll
        for (int nf = 0; nf < 8; nf++) {
            int row = row0 + wm * 32 + mf * 16 + g;
            int col = wn * 64 + nf * 8 + 2 * c4;
            *(float2*)(C + (size_t)row * 128 + col) =
                make_float2(acc[mf][nf][0], acc[mf][nf][1]);
            *(float2*)(C + (size_t)(row + 8) * 128 + col) =
                make_float2(acc[mf][nf][2], acc[mf][nf][3]);
        }

    if (mode == 1) {
#pragma unroll
        for (int nf = 0; nf < 8; nf++) {
            int col = wn * 64 + nf * 8 + 2 * c4;
            float v00 = acc[0][nf][0], v02 = acc[0][nf][2];
            float v10 = acc[1][nf][0], v12 = acc[1][nf][2];
            atomicAdd(&s_sum[col], v00 + v02 + v10 + v12);
            atomicAdd(&s_sq[col], v00 * v00 + v02 * v02 + v10 * v10 + v12 * v12);
            float v01 = acc[0][nf][1], v03 = acc[0][nf][3];
            float v11 = acc[1][nf][1], v13 = acc[1][nf][3];
            atomicAdd(&s_sum[col + 1], v01 + v03 + v11 + v13);
            atomicAdd(&s_sq[col + 1], v01 * v01 + v03 * v03 + v11 * v11 + v13 * v13);
        }
        __syncthreads();
        if (t < 128) {
            atomicAdd(&g_stat[256 + t], s_sum[t]);
            atomicAdd(&g_stat[384 + t], s_sq[t]);
        }
    }
}

// ---------------- k_out: aff2 + leaky + softmax + weighted V sum ----------------
__global__ void k_out(const float* __restrict__ bv,
                      const float* __restrict__ g2, const float* __restrict__ b2,
                      float invc, float* __restrict__ out, int N) {
    int n = blockIdx.x;
    int c = threadIdx.x;
    __shared__ int sidx[KNN];
    if (c < KNN) sidx[c] = g_idx[n * KNN + c];
    __syncthreads();

    float mean2 = g_stat[256 + c] * invc;
    float var2  = g_stat[384 + c] * invc - mean2 * mean2;
    float sc2 = g2[c] * rsqrtf(var2 + EPS);
    float sh2 = b2[c] - mean2 * sc2;

    float tv[KNN];
    float m = -1e30f;
#pragma unroll
    for (int k = 0; k < KNN; k++) {
        float x = g_w2[(size_t)(n * KNN + k) * 128 + c];
        x = fmaf(x, sc2, sh2);
        x = x >= 0.f ? x : SLOPE * x;
        tv[k] = x;
        m = fmaxf(m, x);
    }
    float s = 0.f;
#pragma unroll
    for (int k = 0; k < KNN; k++) { float e = __expf(tv[k] - m); tv[k] = e; s += e; }
    float inv = 1.f / s;
    float b = bv[c];
    float acc = 0.f;
#pragma unroll
    for (int k = 0; k < KNN; k++) {
        float v = g_V[(size_t)sidx[k] * 128 + c] + b;
        acc = fmaf(tv[k] * inv, v, acc);
    }
    out[(size_t)n * 128 + c] = acc;
}

// ---------------- launch ----------------
extern "C" void kernel_launch(void* const* d_in, const int* in_sizes, int n_in,
                              void* d_out, int out_size) {
    const float* fea_i    = (const float*)d_in[0];
    const float* fea_last = (const float*)d_in[1];
    const float* xyz_i    = (const float*)d_in[2];
    const float* xyz_last = (const float*)d_in[3];
    const float* Wq = (const float*)d_in[5];
    const float* Wk = (const float*)d_in[7];
    const float* Wv = (const float*)d_in[9];
    const float* bv = (const float*)d_in[10];
    const float* g1 = (const float*)d_in[11];
    const float* b1 = (const float*)d_in[12];
    const float* Wl = (const float*)d_in[13];
    const float* g2 = (const float*)d_in[15];
    const float* b2 = (const float*)d_in[16];

    int N = in_sizes[0] / CIN;
    float invc = 1.0f / (float)(N * KNN);

    cudaFuncSetAttribute(k_mma_gemm, cudaFuncAttributeMaxDynamicSharedMemorySize, SMEM_TOTAL);

    k_build<<<9, 1024>>>(xyz_i, Wq, Wk, Wv, Wl, N);                 // idx 0

    dim3 gq(N / 128, 3);
    k_mma_gemm<<<gq, 256, SMEM_TOTAL>>>(0, fea_i, fea_last, g1, b1, invc);  // idx 1

    k_knn_warp<<<(N + 7) / 8, 256>>>(xyz_last, N);                  // idx 2 (knn + BN1 stats)

    k_mma_gemm<<<N * KNN / 128, 256, SMEM_TOTAL>>>(1, fea_i, fea_last, g1, b1, invc); // idx 3 (profiled)

    k_out<<<N, 128>>>(bv, g2, b2, invc, (float*)d_out, N);          // idx 4
}